// round 1
// baseline (speedup 1.0000x reference)
#include <cuda_runtime.h>
#include <math.h>
#include <stdint.h>

// ---------------- problem constants ----------------
constexpr int B = 8;
constexpr int T = 769;          // N_KEEP + 1
constexpr int D = 512;
constexpr int H = 8;
constexpr int DH = 64;          // D / H
constexpr int NCOLS = 2048;
constexpr int DCOL = 22;
constexpr int DCOLP = 24;       // padded (float4-friendly, 96B rows)
constexpr int BT = B * T;                       // 6152
constexpr long long X_ELEMS = (long long)BT * D; // 3,149,824 (x output elems)

// ---------------- scratch (device globals; no allocations allowed) ----------------
__device__ float g_fh[BT * D];
__device__ float g_ft[BT * D];
__device__ float g_fv[BT * D];
__device__ float g_xatt[BT * D];
__device__ float g_ch[B * H * T * DCOLP];
__device__ float g_ct[B * H * T * DCOLP];

// ---------------- SGEMM: C[M,512] = A[M,512] @ W[512,512]^T + bias (optional *scale) ----------------
// 128x128 block tile, BK=8, 256 threads, 8x8 microtile.
__global__ __launch_bounds__(256) void sgemm_kernel(
    const float* __restrict__ A, const float* __restrict__ W,
    const float* __restrict__ bias, const float* __restrict__ scale,
    float* __restrict__ C, int M)
{
    __shared__ float As[8][128];
    __shared__ float Bs[8][128];
    const int tid = threadIdx.x;
    const int bm = blockIdx.y, bn = blockIdx.x;
    const int tm = tid >> 4, tn = tid & 15;
    const int lr = tid >> 1, lk = (tid & 1) * 4;
    const int arow = bm * 128 + lr;
    const int brow = bn * 128 + lr;   // N = 512 always divisible
    float acc[8][8];
#pragma unroll
    for (int i = 0; i < 8; i++)
#pragma unroll
        for (int j = 0; j < 8; j++) acc[i][j] = 0.f;

    for (int k0 = 0; k0 < 512; k0 += 8) {
        float4 av = make_float4(0.f, 0.f, 0.f, 0.f);
        if (arow < M) av = *reinterpret_cast<const float4*>(A + (size_t)arow * 512 + k0 + lk);
        float4 bv = *reinterpret_cast<const float4*>(W + (size_t)brow * 512 + k0 + lk);
        __syncthreads();
        As[lk + 0][lr] = av.x; As[lk + 1][lr] = av.y; As[lk + 2][lr] = av.z; As[lk + 3][lr] = av.w;
        Bs[lk + 0][lr] = bv.x; Bs[lk + 1][lr] = bv.y; Bs[lk + 2][lr] = bv.z; Bs[lk + 3][lr] = bv.w;
        __syncthreads();
#pragma unroll
        for (int kk = 0; kk < 8; kk++) {
            float4 a0 = *reinterpret_cast<const float4*>(&As[kk][tm * 4]);
            float4 a1 = *reinterpret_cast<const float4*>(&As[kk][64 + tm * 4]);
            float4 b0 = *reinterpret_cast<const float4*>(&Bs[kk][tn * 4]);
            float4 b1 = *reinterpret_cast<const float4*>(&Bs[kk][64 + tn * 4]);
            float a[8] = {a0.x, a0.y, a0.z, a0.w, a1.x, a1.y, a1.z, a1.w};
            float bb[8] = {b0.x, b0.y, b0.z, b0.w, b1.x, b1.y, b1.z, b1.w};
#pragma unroll
            for (int i = 0; i < 8; i++)
#pragma unroll
                for (int j = 0; j < 8; j++)
                    acc[i][j] = fmaf(a[i], bb[j], acc[i][j]);
        }
    }
#pragma unroll
    for (int i = 0; i < 8; i++) {
        int r = bm * 128 + ((i < 4) ? (tm * 4 + i) : (64 + tm * 4 + i - 4));
        if (r >= M) continue;
#pragma unroll
        for (int j = 0; j < 8; j++) {
            int c = bn * 128 + ((j < 4) ? (tn * 4 + j) : (64 + tn * 4 + j - 4));
            float v = acc[i][j] + bias[c];
            if (scale) v *= scale[c];
            C[(size_t)r * 512 + c] = v;
        }
    }
}

// ---------------- gather + L2-normalize column embeddings ----------------
// ch/ct: [(b*H+h)*T + q][DCOLP]; row 0 = CLS (col row 0), q>=1 -> col row ids[b][q-1]+1
__global__ void gather_kernel(const float* __restrict__ colh, const float* __restrict__ colt,
                              const int* __restrict__ ids,
                              float* __restrict__ ch, float* __restrict__ ct)
{
    int idx = blockIdx.x * blockDim.x + threadIdx.x;
    if (idx >= B * H * T) return;
    int q = idx % T;
    int bh = idx / T;
    int h = bh & 7, b = bh >> 3;
    int srow = (q == 0) ? 0 : (ids[b * (T - 1) + (q - 1)] + 1);
    const float* s1 = colh + ((size_t)h * NCOLS + srow) * DCOL;
    const float* s2 = colt + ((size_t)h * NCOLS + srow) * DCOL;
    float v1[DCOL], v2[DCOL];
    float ss1 = 0.f, ss2 = 0.f;
#pragma unroll
    for (int c = 0; c < DCOL; c++) {
        v1[c] = s1[c]; ss1 += v1[c] * v1[c];
        v2[c] = s2[c]; ss2 += v2[c] * v2[c];
    }
    float n1 = sqrtf(ss1), n2 = sqrtf(ss2);
    float* o1 = ch + (size_t)idx * DCOLP;
    float* o2 = ct + (size_t)idx * DCOLP;
#pragma unroll
    for (int c = 0; c < DCOL; c++) { o1[c] = v1[c] / n1; o2[c] = v2[c] / n2; }
    o1[22] = 0.f; o1[23] = 0.f; o2[22] = 0.f; o2[23] = 0.f;
}

// ---------------- logits: weight_score/8 + adjacency mask -> FR (pre-softmax) ----------------
// Per (bh, 128x128 tile): phase A = 22-d adjacency dot (fp32, hard threshold),
// phase B = 64-d score dot. Adjacency kept as 64-bit mask to bound registers.
__global__ __launch_bounds__(256) void logits_kernel(
    const float* __restrict__ fh, const float* __restrict__ ft,
    const float* __restrict__ ch, const float* __restrict__ ct,
    const float* __restrict__ bias, float* __restrict__ FR)
{
    __shared__ float As[8][128];
    __shared__ float Bs[8][128];
    const int tid = threadIdx.x;
    const int bh = blockIdx.z;
    const int b = bh >> 3, h = bh & 7;
    const int q0 = blockIdx.y * 128, k0 = blockIdx.x * 128;
    const int tm = tid >> 4, tn = tid & 15;
    const int lr = tid >> 1, lk = (tid & 1) * 4;

    int qg[8], kg[8];
#pragma unroll
    for (int i = 0; i < 4; i++) {
        qg[i] = q0 + tm * 4 + i;       qg[i + 4] = q0 + 64 + tm * 4 + i;
        kg[i] = k0 + tn * 4 + i;       kg[i + 4] = k0 + 64 + tn * 4 + i;
    }

    float acc[8][8];
#pragma unroll
    for (int i = 0; i < 8; i++)
#pragma unroll
        for (int j = 0; j < 8; j++) acc[i][j] = 0.f;

    const int qa = q0 + lr, ka = k0 + lr;

    // ---- phase A: top_score (22-d padded to 24) ----
    {
        const float* chb = ch + (size_t)bh * T * DCOLP;
        const float* ctb = ct + (size_t)bh * T * DCOLP;
        for (int kk0 = 0; kk0 < DCOLP; kk0 += 8) {
            float4 av = make_float4(0.f, 0.f, 0.f, 0.f);
            float4 bv = make_float4(0.f, 0.f, 0.f, 0.f);
            if (qa < T) av = *reinterpret_cast<const float4*>(chb + (size_t)qa * DCOLP + kk0 + lk);
            if (ka < T) bv = *reinterpret_cast<const float4*>(ctb + (size_t)ka * DCOLP + kk0 + lk);
            __syncthreads();
            As[lk + 0][lr] = av.x; As[lk + 1][lr] = av.y; As[lk + 2][lr] = av.z; As[lk + 3][lr] = av.w;
            Bs[lk + 0][lr] = bv.x; Bs[lk + 1][lr] = bv.y; Bs[lk + 2][lr] = bv.z; Bs[lk + 3][lr] = bv.w;
            __syncthreads();
#pragma unroll
            for (int kk = 0; kk < 8; kk++) {
                float4 a0 = *reinterpret_cast<const float4*>(&As[kk][tm * 4]);
                float4 a1 = *reinterpret_cast<const float4*>(&As[kk][64 + tm * 4]);
                float4 b0 = *reinterpret_cast<const float4*>(&Bs[kk][tn * 4]);
                float4 b1 = *reinterpret_cast<const float4*>(&Bs[kk][64 + tn * 4]);
                float a[8] = {a0.x, a0.y, a0.z, a0.w, a1.x, a1.y, a1.z, a1.w};
                float bb[8] = {b0.x, b0.y, b0.z, b0.w, b1.x, b1.y, b1.z, b1.w};
#pragma unroll
                for (int i = 0; i < 8; i++)
#pragma unroll
                    for (int j = 0; j < 8; j++)
                        acc[i][j] = fmaf(a[i], bb[j], acc[i][j]);
            }
        }
    }
    const float bias0 = bias[0];
    unsigned long long adjm = 0ull;
#pragma unroll
    for (int i = 0; i < 8; i++)
#pragma unroll
        for (int j = 0; j < 8; j++) {
            // sigmoid(ts + bias) > 0.5  <=>  ts + bias > 0 ; diag & readout column masked out
            bool a = (kg[j] != qg[i]) && (kg[j] != 0) && (acc[i][j] + bias0 > 0.0f);
            if (a) adjm |= (1ull << (i * 8 + j));
        }

    // ---- phase B: weight_score (64-d) ----
#pragma unroll
    for (int i = 0; i < 8; i++)
#pragma unroll
        for (int j = 0; j < 8; j++) acc[i][j] = 0.f;
    {
        const float* fhb = fh + (size_t)b * T * 512 + h * 64;
        const float* ftb = ft + (size_t)b * T * 512 + h * 64;
        for (int kk0 = 0; kk0 < 64; kk0 += 8) {
            float4 av = make_float4(0.f, 0.f, 0.f, 0.f);
            float4 bv = make_float4(0.f, 0.f, 0.f, 0.f);
            if (qa < T) av = *reinterpret_cast<const float4*>(fhb + (size_t)qa * 512 + kk0 + lk);
            if (ka < T) bv = *reinterpret_cast<const float4*>(ftb + (size_t)ka * 512 + kk0 + lk);
            __syncthreads();
            As[lk + 0][lr] = av.x; As[lk + 1][lr] = av.y; As[lk + 2][lr] = av.z; As[lk + 3][lr] = av.w;
            Bs[lk + 0][lr] = bv.x; Bs[lk + 1][lr] = bv.y; Bs[lk + 2][lr] = bv.z; Bs[lk + 3][lr] = bv.w;
            __syncthreads();
#pragma unroll
            for (int kk = 0; kk < 8; kk++) {
                float4 a0 = *reinterpret_cast<const float4*>(&As[kk][tm * 4]);
                float4 a1 = *reinterpret_cast<const float4*>(&As[kk][64 + tm * 4]);
                float4 b0 = *reinterpret_cast<const float4*>(&Bs[kk][tn * 4]);
                float4 b1 = *reinterpret_cast<const float4*>(&Bs[kk][64 + tn * 4]);
                float a[8] = {a0.x, a0.y, a0.z, a0.w, a1.x, a1.y, a1.z, a1.w};
                float bb[8] = {b0.x, b0.y, b0.z, b0.w, b1.x, b1.y, b1.z, b1.w};
#pragma unroll
                for (int i = 0; i < 8; i++)
#pragma unroll
                    for (int j = 0; j < 8; j++)
                        acc[i][j] = fmaf(a[i], bb[j], acc[i][j]);
            }
        }
    }

    // ---- epilogue: logit = ws/8 + (adj ? 0 : -10000) ----
#pragma unroll
    for (int i = 0; i < 8; i++) {
        if (qg[i] >= T) continue;
        float* row = FR + ((size_t)bh * T + qg[i]) * T;
#pragma unroll
        for (int j = 0; j < 8; j++) {
            if (kg[j] >= T) continue;
            float v = acc[i][j] * 0.125f;
            if (!((adjm >> (i * 8 + j)) & 1ull)) v -= 10000.0f;
            row[kg[j]] = v;
        }
    }
}

// ---------------- softmax: in-place over each FR row (length T) ----------------
__global__ __launch_bounds__(256) void softmax_kernel(float* __restrict__ FR)
{
    __shared__ float sred[8];
    const int tid = threadIdx.x;
    const int wid = tid >> 5, lane = tid & 31;
    float* base = FR + (size_t)blockIdx.x * T;

    float v[4];
    int n = 0;
    float m = -3.0e38f;
    for (int i = tid; i < T; i += 256) { v[n] = base[i]; m = fmaxf(m, v[n]); n++; }
#pragma unroll
    for (int o = 16; o; o >>= 1) m = fmaxf(m, __shfl_xor_sync(0xffffffffu, m, o));
    if (lane == 0) sred[wid] = m;
    __syncthreads();
    m = sred[0];
#pragma unroll
    for (int w = 1; w < 8; w++) m = fmaxf(m, sred[w]);
    __syncthreads();

    float e[4];
    float s = 0.f;
    for (int i = 0; i < n; i++) { e[i] = expf(v[i] - m); s += e[i]; }
#pragma unroll
    for (int o = 16; o; o >>= 1) s += __shfl_xor_sync(0xffffffffu, s, o);
    if (lane == 0) sred[wid] = s;
    __syncthreads();
    s = 0.f;
#pragma unroll
    for (int w = 0; w < 8; w++) s += sred[w];
    float inv = 1.0f / s;
    n = 0;
    for (int i = tid; i < T; i += 256) { base[i] = e[n] * inv; n++; }
}

// ---------------- AV: xatt[b,q, h*64+d] = sum_k P[bh,q,k] * fv[b,k, h*64+d] ----------------
// Block: (q-tile of 128) x (bh). 256 threads, 8x4 microtile over [128 x 64].
__global__ __launch_bounds__(256) void av_kernel(
    const float* __restrict__ P, const float* __restrict__ fv, float* __restrict__ xatt)
{
    __shared__ float Ps[8][128];
    __shared__ float Vs[8][64];
    const int tid = threadIdx.x;
    const int bh = blockIdx.y, b = bh >> 3, h = bh & 7;
    const int q0 = blockIdx.x * 128;
    const int tm = tid >> 4, tn = tid & 15;
    const int lr = tid >> 1, lk = (tid & 1) * 4;
    const int vkr = tid >> 5, vdc = (tid & 31) * 2;
    const float* Pb = P + (size_t)bh * T * T;
    const float* Vb = fv + (size_t)b * T * 512 + h * 64;
    float acc[8][4];
#pragma unroll
    for (int i = 0; i < 8; i++)
#pragma unroll
        for (int j = 0; j < 4; j++) acc[i][j] = 0.f;

    const int qa = q0 + lr;
    for (int k0 = 0; k0 < T; k0 += 8) {
        float pv[4];
#pragma unroll
        for (int c = 0; c < 4; c++) {
            int k = k0 + lk + c;
            pv[c] = (qa < T && k < T) ? Pb[(size_t)qa * T + k] : 0.f;
        }
        int kv = k0 + vkr;
        float2 vvv = make_float2(0.f, 0.f);
        if (kv < T) vvv = *reinterpret_cast<const float2*>(Vb + (size_t)kv * 512 + vdc);
        __syncthreads();
#pragma unroll
        for (int c = 0; c < 4; c++) Ps[lk + c][lr] = pv[c];
        Vs[vkr][vdc] = vvv.x; Vs[vkr][vdc + 1] = vvv.y;
        __syncthreads();
#pragma unroll
        for (int kk = 0; kk < 8; kk++) {
            float4 a0 = *reinterpret_cast<const float4*>(&Ps[kk][tm * 8]);
            float4 a1 = *reinterpret_cast<const float4*>(&Ps[kk][tm * 8 + 4]);
            float4 bq = *reinterpret_cast<const float4*>(&Vs[kk][tn * 4]);
            float a[8] = {a0.x, a0.y, a0.z, a0.w, a1.x, a1.y, a1.z, a1.w};
            float bb[4] = {bq.x, bq.y, bq.z, bq.w};
#pragma unroll
            for (int i = 0; i < 8; i++)
#pragma unroll
                for (int j = 0; j < 4; j++)
                    acc[i][j] = fmaf(a[i], bb[j], acc[i][j]);
        }
    }
#pragma unroll
    for (int i = 0; i < 8; i++) {
        int q = q0 + tm * 8 + i;
        if (q >= T) continue;
#pragma unroll
        for (int j = 0; j < 4; j++)
            xatt[((size_t)b * T + q) * 512 + h * 64 + tn * 4 + j] = acc[i][j];
    }
}

// ---------------- launcher ----------------
extern "C" void kernel_launch(void* const* d_in, const int* in_sizes, int n_in,
                              void* d_out, int out_size)
{
    const float* x_head = (const float*)d_in[0];
    const float* x_tail = (const float*)d_in[1];
    const int*   ids    = (const int*)  d_in[2];
    const float* Wh     = (const float*)d_in[3];
    const float* bh     = (const float*)d_in[4];
    const float* Wv     = (const float*)d_in[5];
    const float* bv     = (const float*)d_in[6];
    const float* Wo     = (const float*)d_in[7];
    const float* bo     = (const float*)d_in[8];
    const float* rel    = (const float*)d_in[9];   // [H,64] contiguous = 512-vec
    const float* colh   = (const float*)d_in[10];
    const float* colt   = (const float*)d_in[11];
    const float* bias   = (const float*)d_in[12];

    float* out = (float*)d_out;            // x: [B,T,D]
    float* FR  = out + X_ELEMS;            // fr_graph: [B,H,T,T]

    float *p_fh, *p_ft, *p_fv, *p_xatt, *p_ch, *p_ct;
    cudaGetSymbolAddress((void**)&p_fh, g_fh);
    cudaGetSymbolAddress((void**)&p_ft, g_ft);
    cudaGetSymbolAddress((void**)&p_fv, g_fv);
    cudaGetSymbolAddress((void**)&p_xatt, g_xatt);
    cudaGetSymbolAddress((void**)&p_ch, g_ch);
    cudaGetSymbolAddress((void**)&p_ct, g_ct);

    dim3 gProj(4, (BT + 127) / 128);   // (N tiles, M tiles) = (4, 49)

    // projections: f_head (pre-scaled by rel_emb), f_tail, f_v
    sgemm_kernel<<<gProj, 256>>>(x_head, Wh, bh, rel,     p_fh, BT);
    sgemm_kernel<<<gProj, 256>>>(x_tail, Wh, bh, nullptr, p_ft, BT);
    sgemm_kernel<<<gProj, 256>>>(x_tail, Wv, bv, nullptr, p_fv, BT);

    // gather + normalize column embeddings
    gather_kernel<<<(B * H * T + 255) / 256, 256>>>(colh, colt, ids, p_ch, p_ct);

    // masked logits into FR
    dim3 gLog((T + 127) / 128, (T + 127) / 128, B * H);   // (7,7,64)
    logits_kernel<<<gLog, 256>>>(p_fh, p_ft, p_ch, p_ct, bias, FR);

    // row softmax in place -> fr_graph output
    softmax_kernel<<<B * H * T, 256>>>(FR);

    // attention-weighted values
    dim3 gAV((T + 127) / 128, B * H);   // (7,64)
    av_kernel<<<gAV, 256>>>(FR, p_fv, p_xatt);

    // output projection -> x output
    sgemm_kernel<<<gProj, 256>>>(p_xatt, Wo, bo, nullptr, out, BT);
}

// round 3
// speedup vs baseline: 1.3003x; 1.3003x over previous
#include <cuda_runtime.h>
#include <cuda_bf16.h>
#include <math.h>
#include <stdint.h>

// ---------------- problem constants ----------------
constexpr int B = 8;
constexpr int T = 769;          // N_KEEP + 1
constexpr int H = 8;
constexpr int NCOLS = 2048;
constexpr int DCOL = 22;
constexpr int DCOLP = 24;
constexpr int BT = B * T;                        // 6152
constexpr long long X_ELEMS = (long long)BT * 512;

// ---------------- scratch (device globals; no allocations allowed) ----------------
__device__ float g_fh[BT * 512];
__device__ float g_ft[BT * 512];
__device__ float g_fv[BT * 512];
__device__ float g_xatt[BT * 512];
__device__ float g_ch[B * H * T * DCOLP];
__device__ float g_ct[B * H * T * DCOLP];

// ================= warp-level MMA helpers (plain PTX, sm_80+) =================
__device__ __forceinline__ void ldsm_x4(uint32_t& r0, uint32_t& r1, uint32_t& r2, uint32_t& r3,
                                        uint32_t addr) {
    asm volatile("ldmatrix.sync.aligned.m8n8.x4.shared.b16 {%0,%1,%2,%3}, [%4];"
                 : "=r"(r0), "=r"(r1), "=r"(r2), "=r"(r3) : "r"(addr));
}
__device__ __forceinline__ void mma_bf16(float* c, const uint32_t* a, uint32_t b0, uint32_t b1) {
    asm volatile("mma.sync.aligned.m16n8k16.row.col.f32.bf16.bf16.f32 "
                 "{%0,%1,%2,%3}, {%4,%5,%6,%7}, {%8,%9}, {%0,%1,%2,%3};"
                 : "+f"(c[0]), "+f"(c[1]), "+f"(c[2]), "+f"(c[3])
                 : "r"(a[0]), "r"(a[1]), "r"(a[2]), "r"(a[3]), "r"(b0), "r"(b1));
}
__device__ __forceinline__ uint32_t smem_addr(const void* p) {
    return (uint32_t)__cvta_generic_to_shared(p);
}

// split a float4 into hi/lo bf16 pairs packed as uint2
__device__ __forceinline__ void split4(float4 v, uint2& hi, uint2& lo) {
    float f[4] = {v.x, v.y, v.z, v.w};
    float fh[4], fl[4];
#pragma unroll
    for (int j = 0; j < 4; j++) {
        fh[j] = __bfloat162float(__float2bfloat16_rn(f[j]));
        fl[j] = f[j] - fh[j];
    }
    union { __nv_bfloat162 h2[2]; uint2 u; } a, b;
    a.h2[0] = __floats2bfloat162_rn(fh[0], fh[1]);
    a.h2[1] = __floats2bfloat162_rn(fh[2], fh[3]);
    b.h2[0] = __floats2bfloat162_rn(fl[0], fl[1]);
    b.h2[1] = __floats2bfloat162_rn(fl[2], fl[3]);
    hi = a.u; lo = b.u;
}

// ================= HMMA split-bf16 GEMM =================
// C[M,512] = A[M,512] @ W[512,512]^T + bias (then optional *scale)
// 128x128 CTA tile, BK=32, 8 warps (4m x 2n), warp tile 32x64.
constexpr int LDS_PAD = 40;   // 32 + 8 bf16 (16B) pad; conflict-free ldmatrix

__global__ __launch_bounds__(256) void gemm_hmma_kernel(
    const float* __restrict__ A, const float* __restrict__ W,
    const float* __restrict__ bias, const float* __restrict__ scale,
    float* __restrict__ C, int M)
{
    __shared__ __nv_bfloat16 AsH[128][LDS_PAD], AsL[128][LDS_PAD];
    __shared__ __nv_bfloat16 BsH[128][LDS_PAD], BsL[128][LDS_PAD];

    const int tid = threadIdx.x;
    const int wid = tid >> 5, lane = tid & 31;
    const int wm = wid & 3, wn = wid >> 2;         // 4 m-warps x 2 n-warps
    const int m0 = blockIdx.y * 128, n0 = blockIdx.x * 128;

    float acc[2][8][4];
#pragma unroll
    for (int mi = 0; mi < 2; mi++)
#pragma unroll
        for (int ni = 0; ni < 8; ni++)
#pragma unroll
            for (int r = 0; r < 4; r++) acc[mi][ni][r] = 0.f;

    // smem load indices: s in [0,1024): row = s>>3, col4 = (s&7)*4
    const int lrow = tid >> 3;          // base row for i=0 (rows advance by 32 per i)
    const int lcol = (tid & 7) * 4;

    // ldmatrix lane addresses (A: 16-row x4; B: 8-row x4 spanning k=0..31)
    const int a_r = (lane & 15), a_c = (lane >> 4) * 8;
    const int b_r = (lane & 7),  b_c = (lane >> 3) * 8;

    for (int chunk = 0; chunk < 16; chunk++) {
        const int k0 = chunk * 32;
        __syncthreads();
        // ---- A tile: 128x32 fp32 -> hi/lo bf16
#pragma unroll
        for (int i = 0; i < 4; i++) {
            const int row = lrow + 32 * i;
            const int gr = m0 + row;
            float4 v = make_float4(0.f, 0.f, 0.f, 0.f);
            if (gr < M) v = *(const float4*)(A + (size_t)gr * 512 + k0 + lcol);
            uint2 hi, lo; split4(v, hi, lo);
            *(uint2*)&AsH[row][lcol] = hi;
            *(uint2*)&AsL[row][lcol] = lo;
        }
        // ---- B tile (W rows n0..n0+127): 128x32 fp32 -> hi/lo bf16
#pragma unroll
        for (int i = 0; i < 4; i++) {
            const int row = lrow + 32 * i;
            float4 v = *(const float4*)(W + (size_t)(n0 + row) * 512 + k0 + lcol);
            uint2 hi, lo; split4(v, hi, lo);
            *(uint2*)&BsH[row][lcol] = hi;
            *(uint2*)&BsL[row][lcol] = lo;
        }
        __syncthreads();

        // ---- A fragments: [mi][ks] hi+lo
        uint32_t ah[2][2][4], al[2][2][4];
#pragma unroll
        for (int mi = 0; mi < 2; mi++) {
            const int r = wm * 32 + mi * 16 + a_r;
#pragma unroll
            for (int ks = 0; ks < 2; ks++) {
                const int c = ks * 16 + a_c;
                ldsm_x4(ah[mi][ks][0], ah[mi][ks][1], ah[mi][ks][2], ah[mi][ks][3],
                        smem_addr(&AsH[r][c]));
                ldsm_x4(al[mi][ks][0], al[mi][ks][1], al[mi][ks][2], al[mi][ks][3],
                        smem_addr(&AsL[r][c]));
            }
        }
        // ---- per n-iter: B frags (x4 covers both k-steps), 12 MMAs
#pragma unroll
        for (int ni = 0; ni < 8; ni++) {
            const int r = wn * 64 + ni * 8 + b_r;
            uint32_t bh[4], bl[4];
            ldsm_x4(bh[0], bh[1], bh[2], bh[3], smem_addr(&BsH[r][b_c]));
            ldsm_x4(bl[0], bl[1], bl[2], bl[3], smem_addr(&BsL[r][b_c]));
#pragma unroll
            for (int mi = 0; mi < 2; mi++) {
#pragma unroll
                for (int ks = 0; ks < 2; ks++) {
                    mma_bf16(acc[mi][ni], ah[mi][ks], bh[2 * ks], bh[2 * ks + 1]);
                    mma_bf16(acc[mi][ni], ah[mi][ks], bl[2 * ks], bl[2 * ks + 1]);
                    mma_bf16(acc[mi][ni], al[mi][ks], bh[2 * ks], bh[2 * ks + 1]);
                }
            }
        }
    }

    // ---- epilogue: acc -> C with bias (+ optional scale)
    const int tr = lane >> 2, tc = (lane & 3) * 2;
#pragma unroll
    for (int mi = 0; mi < 2; mi++) {
#pragma unroll
        for (int ni = 0; ni < 8; ni++) {
            const int n = n0 + wn * 64 + ni * 8 + tc;
            float b0 = bias[n], b1 = bias[n + 1];
            float s0 = 1.f, s1 = 1.f;
            if (scale) { s0 = scale[n]; s1 = scale[n + 1]; }
#pragma unroll
            for (int half = 0; half < 2; half++) {
                const int m = m0 + wm * 32 + mi * 16 + tr + half * 8;
                if (m < M) {
                    float2 o;
                    o.x = (acc[mi][ni][half * 2 + 0] + b0) * s0;
                    o.y = (acc[mi][ni][half * 2 + 1] + b1) * s1;
                    *(float2*)(C + (size_t)m * 512 + n) = o;
                }
            }
        }
    }
}

// ---------------- gather + L2-normalize column embeddings ----------------
__global__ void gather_kernel(const float* __restrict__ colh, const float* __restrict__ colt,
                              const int* __restrict__ ids,
                              float* __restrict__ ch, float* __restrict__ ct)
{
    int idx = blockIdx.x * blockDim.x + threadIdx.x;
    if (idx >= B * H * T) return;
    int q = idx % T;
    int bh = idx / T;
    int h = bh & 7, b = bh >> 3;
    int srow = (q == 0) ? 0 : (ids[b * (T - 1) + (q - 1)] + 1);
    const float* s1 = colh + ((size_t)h * NCOLS + srow) * DCOL;
    const float* s2 = colt + ((size_t)h * NCOLS + srow) * DCOL;
    float v1[DCOL], v2[DCOL];
    float ss1 = 0.f, ss2 = 0.f;
#pragma unroll
    for (int c = 0; c < DCOL; c++) {
        v1[c] = s1[c]; ss1 += v1[c] * v1[c];
        v2[c] = s2[c]; ss2 += v2[c] * v2[c];
    }
    float n1 = sqrtf(ss1), n2 = sqrtf(ss2);
    float* o1 = ch + (size_t)idx * DCOLP;
    float* o2 = ct + (size_t)idx * DCOLP;
#pragma unroll
    for (int c = 0; c < DCOL; c++) { o1[c] = v1[c] / n1; o2[c] = v2[c] / n2; }
    o1[22] = 0.f; o1[23] = 0.f; o2[22] = 0.f; o2[23] = 0.f;
}

// ---------------- logits: weight_score/8 + adjacency mask -> FR (pre-softmax) ----------------
__global__ __launch_bounds__(256) void logits_kernel(
    const float* __restrict__ fh, const float* __restrict__ ft,
    const float* __restrict__ ch, const float* __restrict__ ct,
    const float* __restrict__ bias, float* __restrict__ FR)
{
    __shared__ float As[8][128];
    __shared__ float Bs[8][128];
    const int tid = threadIdx.x;
    const int bh = blockIdx.z;
    const int b = bh >> 3, h = bh & 7;
    const int q0 = blockIdx.y * 128, k0 = blockIdx.x * 128;
    const int tm = tid >> 4, tn = tid & 15;
    const int lr = tid >> 1, lk = (tid & 1) * 4;

    int qg[8], kg[8];
#pragma unroll
    for (int i = 0; i < 4; i++) {
        qg[i] = q0 + tm * 4 + i;       qg[i + 4] = q0 + 64 + tm * 4 + i;
        kg[i] = k0 + tn * 4 + i;       kg[i + 4] = k0 + 64 + tn * 4 + i;
    }

    float acc[8][8];
#pragma unroll
    for (int i = 0; i < 8; i++)
#pragma unroll
        for (int j = 0; j < 8; j++) acc[i][j] = 0.f;

    const int qa = q0 + lr, ka = k0 + lr;

    // ---- phase A: top_score (22-d padded to 24) ----
    {
        const float* chb = ch + (size_t)bh * T * DCOLP;
        const float* ctb = ct + (size_t)bh * T * DCOLP;
        for (int kk0 = 0; kk0 < DCOLP; kk0 += 8) {
            float4 av = make_float4(0.f, 0.f, 0.f, 0.f);
            float4 bv = make_float4(0.f, 0.f, 0.f, 0.f);
            if (qa < T) av = *reinterpret_cast<const float4*>(chb + (size_t)qa * DCOLP + kk0 + lk);
            if (ka < T) bv = *reinterpret_cast<const float4*>(ctb + (size_t)ka * DCOLP + kk0 + lk);
            __syncthreads();
            As[lk + 0][lr] = av.x; As[lk + 1][lr] = av.y; As[lk + 2][lr] = av.z; As[lk + 3][lr] = av.w;
            Bs[lk + 0][lr] = bv.x; Bs[lk + 1][lr] = bv.y; Bs[lk + 2][lr] = bv.z; Bs[lk + 3][lr] = bv.w;
            __syncthreads();
#pragma unroll
            for (int kk = 0; kk < 8; kk++) {
                float4 a0 = *reinterpret_cast<const float4*>(&As[kk][tm * 4]);
                float4 a1 = *reinterpret_cast<const float4*>(&As[kk][64 + tm * 4]);
                float4 b0 = *reinterpret_cast<const float4*>(&Bs[kk][tn * 4]);
                float4 b1 = *reinterpret_cast<const float4*>(&Bs[kk][64 + tn * 4]);
                float a[8] = {a0.x, a0.y, a0.z, a0.w, a1.x, a1.y, a1.z, a1.w};
                float bb[8] = {b0.x, b0.y, b0.z, b0.w, b1.x, b1.y, b1.z, b1.w};
#pragma unroll
                for (int i = 0; i < 8; i++)
#pragma unroll
                    for (int j = 0; j < 8; j++)
                        acc[i][j] = fmaf(a[i], bb[j], acc[i][j]);
            }
        }
    }
    const float bias0 = bias[0];
    unsigned long long adjm = 0ull;
#pragma unroll
    for (int i = 0; i < 8; i++)
#pragma unroll
        for (int j = 0; j < 8; j++) {
            bool a = (kg[j] != qg[i]) && (kg[j] != 0) && (acc[i][j] + bias0 > 0.0f);
            if (a) adjm |= (1ull << (i * 8 + j));
        }

    // ---- phase B: weight_score (64-d) ----
#pragma unroll
    for (int i = 0; i < 8; i++)
#pragma unroll
        for (int j = 0; j < 8; j++) acc[i][j] = 0.f;
    {
        const float* fhb = fh + (size_t)b * T * 512 + h * 64;
        const float* ftb = ft + (size_t)b * T * 512 + h * 64;
        for (int kk0 = 0; kk0 < 64; kk0 += 8) {
            float4 av = make_float4(0.f, 0.f, 0.f, 0.f);
            float4 bv = make_float4(0.f, 0.f, 0.f, 0.f);
            if (qa < T) av = *reinterpret_cast<const float4*>(fhb + (size_t)qa * 512 + kk0 + lk);
            if (ka < T) bv = *reinterpret_cast<const float4*>(ftb + (size_t)ka * 512 + kk0 + lk);
            __syncthreads();
            As[lk + 0][lr] = av.x; As[lk + 1][lr] = av.y; As[lk + 2][lr] = av.z; As[lk + 3][lr] = av.w;
            Bs[lk + 0][lr] = bv.x; Bs[lk + 1][lr] = bv.y; Bs[lk + 2][lr] = bv.z; Bs[lk + 3][lr] = bv.w;
            __syncthreads();
#pragma unroll
            for (int kk = 0; kk < 8; kk++) {
                float4 a0 = *reinterpret_cast<const float4*>(&As[kk][tm * 4]);
                float4 a1 = *reinterpret_cast<const float4*>(&As[kk][64 + tm * 4]);
                float4 b0 = *reinterpret_cast<const float4*>(&Bs[kk][tn * 4]);
                float4 b1 = *reinterpret_cast<const float4*>(&Bs[kk][64 + tn * 4]);
                float a[8] = {a0.x, a0.y, a0.z, a0.w, a1.x, a1.y, a1.z, a1.w};
                float bb[8] = {b0.x, b0.y, b0.z, b0.w, b1.x, b1.y, b1.z, b1.w};
#pragma unroll
                for (int i = 0; i < 8; i++)
#pragma unroll
                    for (int j = 0; j < 8; j++)
                        acc[i][j] = fmaf(a[i], bb[j], acc[i][j]);
            }
        }
    }

#pragma unroll
    for (int i = 0; i < 8; i++) {
        if (qg[i] >= T) continue;
        float* row = FR + ((size_t)bh * T + qg[i]) * T;
#pragma unroll
        for (int j = 0; j < 8; j++) {
            if (kg[j] >= T) continue;
            float v = acc[i][j] * 0.125f;
            if (!((adjm >> (i * 8 + j)) & 1ull)) v -= 10000.0f;
            row[kg[j]] = v;
        }
    }
}

// ---------------- softmax: in-place over each FR row (length T) ----------------
__global__ __launch_bounds__(256) void softmax_kernel(float* __restrict__ FR)
{
    __shared__ float sred[8];
    const int tid = threadIdx.x;
    const int wid = tid >> 5, lane = tid & 31;
    float* base = FR + (size_t)blockIdx.x * T;

    float v[4];
    int n = 0;
    float m = -3.0e38f;
    for (int i = tid; i < T; i += 256) { v[n] = base[i]; m = fmaxf(m, v[n]); n++; }
#pragma unroll
    for (int o = 16; o; o >>= 1) m = fmaxf(m, __shfl_xor_sync(0xffffffffu, m, o));
    if (lane == 0) sred[wid] = m;
    __syncthreads();
    m = sred[0];
#pragma unroll
    for (int w = 1; w < 8; w++) m = fmaxf(m, sred[w]);
    __syncthreads();

    float e[4];
    float s = 0.f;
    for (int i = 0; i < n; i++) { e[i] = expf(v[i] - m); s += e[i]; }
#pragma unroll
    for (int o = 16; o; o >>= 1) s += __shfl_xor_sync(0xffffffffu, s, o);
    if (lane == 0) sred[wid] = s;
    __syncthreads();
    s = 0.f;
#pragma unroll
    for (int w = 0; w < 8; w++) s += sred[w];
    float inv = 1.0f / s;
    n = 0;
    for (int i = tid; i < T; i += 256) { base[i] = e[n] * inv; n++; }
}

// ---------------- AV: xatt[b,q, h*64+d] = sum_k P[bh,q,k] * fv[b,k, h*64+d] ----------------
__global__ __launch_bounds__(256) void av_kernel(
    const float* __restrict__ P, const float* __restrict__ fv, float* __restrict__ xatt)
{
    __shared__ float Ps[8][128];
    __shared__ float Vs[8][64];
    const int tid = threadIdx.x;
    const int bh = blockIdx.y, b = bh >> 3, h = bh & 7;
    const int q0 = blockIdx.x * 128;
    const int tm = tid >> 4, tn = tid & 15;
    const int lr = tid >> 1, lk = (tid & 1) * 4;
    const int vkr = tid >> 5, vdc = (tid & 31) * 2;
    const float* Pb = P + (size_t)bh * T * T;
    const float* Vb = fv + (size_t)b * T * 512 + h * 64;
    float acc[8][4];
#pragma unroll
    for (int i = 0; i < 8; i++)
#pragma unroll
        for (int j = 0; j < 4; j++) acc[i][j] = 0.f;

    const int qa = q0 + lr;
    for (int k0 = 0; k0 < T; k0 += 8) {
        float pv[4];
#pragma unroll
        for (int c = 0; c < 4; c++) {
            int k = k0 + lk + c;
            pv[c] = (qa < T && k < T) ? Pb[(size_t)qa * T + k] : 0.f;
        }
        int kv = k0 + vkr;
        float2 vvv = make_float2(0.f, 0.f);
        if (kv < T) vvv = *reinterpret_cast<const float2*>(Vb + (size_t)kv * 512 + vdc);
        __syncthreads();
#pragma unroll
        for (int c = 0; c < 4; c++) Ps[lk + c][lr] = pv[c];
        Vs[vkr][vdc] = vvv.x; Vs[vkr][vdc + 1] = vvv.y;
        __syncthreads();
#pragma unroll
        for (int kk = 0; kk < 8; kk++) {
            float4 a0 = *reinterpret_cast<const float4*>(&Ps[kk][tm * 8]);
            float4 a1 = *reinterpret_cast<const float4*>(&Ps[kk][tm * 8 + 4]);
            float4 bq = *reinterpret_cast<const float4*>(&Vs[kk][tn * 4]);
            float a[8] = {a0.x, a0.y, a0.z, a0.w, a1.x, a1.y, a1.z, a1.w};
            float bb[4] = {bq.x, bq.y, bq.z, bq.w};
#pragma unroll
            for (int i = 0; i < 8; i++)
#pragma unroll
                for (int j = 0; j < 4; j++)
                    acc[i][j] = fmaf(a[i], bb[j], acc[i][j]);
        }
    }
#pragma unroll
    for (int i = 0; i < 8; i++) {
        int q = q0 + tm * 8 + i;
        if (q >= T) continue;
#pragma unroll
        for (int j = 0; j < 4; j++)
            xatt[((size_t)b * T + q) * 512 + h * 64 + tn * 4 + j] = acc[i][j];
    }
}

// ---------------- launcher ----------------
extern "C" void kernel_launch(void* const* d_in, const int* in_sizes, int n_in,
                              void* d_out, int out_size)
{
    const float* x_head = (const float*)d_in[0];
    const float* x_tail = (const float*)d_in[1];
    const int*   ids    = (const int*)  d_in[2];
    const float* Wh     = (const float*)d_in[3];
    const float* bh     = (const float*)d_in[4];
    const float* Wv     = (const float*)d_in[5];
    const float* bv     = (const float*)d_in[6];
    const float* Wo     = (const float*)d_in[7];
    const float* bo     = (const float*)d_in[8];
    const float* rel    = (const float*)d_in[9];   // [H,64] contiguous = 512-vec
    const float* colh   = (const float*)d_in[10];
    const float* colt   = (const float*)d_in[11];
    const float* bias   = (const float*)d_in[12];

    float* out = (float*)d_out;            // x: [B,T,D]
    float* FR  = out + X_ELEMS;            // fr_graph: [B,H,T,T]

    float *p_fh, *p_ft, *p_fv, *p_xatt, *p_ch, *p_ct;
    cudaGetSymbolAddress((void**)&p_fh, g_fh);
    cudaGetSymbolAddress((void**)&p_ft, g_ft);
    cudaGetSymbolAddress((void**)&p_fv, g_fv);
    cudaGetSymbolAddress((void**)&p_xatt, g_xatt);
    cudaGetSymbolAddress((void**)&p_ch, g_ch);
    cudaGetSymbolAddress((void**)&p_ct, g_ct);

    dim3 gProj(4, (BT + 127) / 128);   // (N tiles=4, M tiles=49)

    // projections on HMMA tensor path: f_head (scaled by rel_emb), f_tail, f_v
    gemm_hmma_kernel<<<gProj, 256>>>(x_head, Wh, bh, rel,     p_fh, BT);
    gemm_hmma_kernel<<<gProj, 256>>>(x_tail, Wh, bh, nullptr, p_ft, BT);
    gemm_hmma_kernel<<<gProj, 256>>>(x_tail, Wv, bv, nullptr, p_fv, BT);

    // gather + normalize column embeddings
    gather_kernel<<<(B * H * T + 255) / 256, 256>>>(colh, colt, ids, p_ch, p_ct);

    // masked logits into FR
    dim3 gLog((T + 127) / 128, (T + 127) / 128, B * H);   // (7,7,64)
    logits_kernel<<<gLog, 256>>>(p_fh, p_ft, p_ch, p_ct, bias, FR);

    // row softmax in place -> fr_graph output
    softmax_kernel<<<B * H * T, 256>>>(FR);

    // attention-weighted values
    dim3 gAV((T + 127) / 128, B * H);   // (7,64)
    av_kernel<<<gAV, 256>>>(FR, p_fv, p_xatt);

    // output projection -> x output
    gemm_hmma_kernel<<<gProj, 256>>>(p_xatt, Wo, bo, nullptr, out, BT);
}

// round 5
// speedup vs baseline: 1.3258x; 1.0196x over previous
#include <cuda_runtime.h>
#include <cuda_bf16.h>
#include <math.h>
#include <stdint.h>

// ---------------- problem constants ----------------
constexpr int B = 8;
constexpr int T = 769;
constexpr int H = 8;
constexpr int NCOLS = 2048;
constexpr int BT = B * T;            // 6152
constexpr int BHT = B * H * T;       // 49216
constexpr int TP = 800;              // padded T for P planes
constexpr long long X_ELEMS = (long long)BT * 512;

// ---------------- scratch (device globals; zero-initialized) ----------------
__device__ __nv_bfloat16 g_xhH[BT * 512], g_xhL[BT * 512];
__device__ __nv_bfloat16 g_xtH[BT * 512], g_xtL[BT * 512];
__device__ __nv_bfloat16 g_WhH[512 * 512], g_WhL[512 * 512];
__device__ __nv_bfloat16 g_WvH[512 * 512], g_WvL[512 * 512];
__device__ __nv_bfloat16 g_WoH[512 * 512], g_WoL[512 * 512];
__device__ __nv_bfloat16 g_fhH[BT * 512], g_fhL[BT * 512];
__device__ __nv_bfloat16 g_ftH[BT * 512], g_ftL[BT * 512];
__device__ __nv_bfloat16 g_fvH[BT * 512], g_fvL[BT * 512];
__device__ __nv_bfloat16 g_xaH[BT * 512], g_xaL[BT * 512];
__device__ __nv_bfloat16 g_chH[BHT * 32], g_chL[BHT * 32];
__device__ __nv_bfloat16 g_ctH[BHT * 32], g_ctL[BHT * 32];
__device__ float g_chf[BHT * 24], g_ctf[BHT * 24];
__device__ __nv_bfloat16 g_pH[(size_t)BHT * TP], g_pL[(size_t)BHT * TP];  // padded P planes

// ================= warp MMA helpers =================
__device__ __forceinline__ void ldsm_x4(uint32_t* r, uint32_t addr) {
    asm volatile("ldmatrix.sync.aligned.m8n8.x4.shared.b16 {%0,%1,%2,%3}, [%4];"
                 : "=r"(r[0]), "=r"(r[1]), "=r"(r[2]), "=r"(r[3]) : "r"(addr));
}
__device__ __forceinline__ void ldsm_x4_t(uint32_t* r, uint32_t addr) {
    asm volatile("ldmatrix.sync.aligned.m8n8.x4.trans.shared.b16 {%0,%1,%2,%3}, [%4];"
                 : "=r"(r[0]), "=r"(r[1]), "=r"(r[2]), "=r"(r[3]) : "r"(addr));
}
__device__ __forceinline__ void mma_bf16(float* c, const uint32_t* a, uint32_t b0, uint32_t b1) {
    asm volatile("mma.sync.aligned.m16n8k16.row.col.f32.bf16.bf16.f32 "
                 "{%0,%1,%2,%3}, {%4,%5,%6,%7}, {%8,%9}, {%0,%1,%2,%3};"
                 : "+f"(c[0]), "+f"(c[1]), "+f"(c[2]), "+f"(c[3])
                 : "r"(a[0]), "r"(a[1]), "r"(a[2]), "r"(a[3]), "r"(b0), "r"(b1));
}
__device__ __forceinline__ uint32_t smem_addr(const void* p) {
    return (uint32_t)__cvta_generic_to_shared(p);
}
__device__ __forceinline__ void split4(float4 v, uint2& hi, uint2& lo) {
    float f[4] = {v.x, v.y, v.z, v.w};
    float fh[4], fl[4];
#pragma unroll
    for (int j = 0; j < 4; j++) {
        fh[j] = __bfloat162float(__float2bfloat16_rn(f[j]));
        fl[j] = f[j] - fh[j];
    }
    union { __nv_bfloat162 h2[2]; uint2 u; } a, b;
    a.h2[0] = __floats2bfloat162_rn(fh[0], fh[1]);
    a.h2[1] = __floats2bfloat162_rn(fh[2], fh[3]);
    b.h2[0] = __floats2bfloat162_rn(fl[0], fl[1]);
    b.h2[1] = __floats2bfloat162_rn(fl[2], fl[3]);
    hi = a.u; lo = b.u;
}
__device__ __forceinline__ void split2(float x, float y, uint32_t& hi, uint32_t& lo) {
    float hx = __bfloat162float(__float2bfloat16_rn(x));
    float hy = __bfloat162float(__float2bfloat16_rn(y));
    union { __nv_bfloat162 h2; uint32_t u; } a, b;
    a.h2 = __floats2bfloat162_rn(hx, hy);
    b.h2 = __floats2bfloat162_rn(x - hx, y - hy);
    hi = a.u; lo = b.u;
}

// ================= convert: fp32 -> hi/lo bf16 planes =================
__global__ void convert_kernel(const float* __restrict__ in,
                               __nv_bfloat16* __restrict__ hi, __nv_bfloat16* __restrict__ lo,
                               int n4)
{
    int i = blockIdx.x * blockDim.x + threadIdx.x;
    if (i >= n4) return;
    float4 v = ((const float4*)in)[i];
    uint2 h, l; split4(v, h, l);
    ((uint2*)hi)[i] = h;
    ((uint2*)lo)[i] = l;
}

// ================= HMMA split-bf16 GEMM (bf16-plane operands) =================
__global__ __launch_bounds__(256) void gemm_hmma2(
    const __nv_bfloat16* __restrict__ AH, const __nv_bfloat16* __restrict__ AL,
    const __nv_bfloat16* __restrict__ WH, const __nv_bfloat16* __restrict__ WL,
    const float* __restrict__ bias, const float* __restrict__ scale,
    float* __restrict__ Cf, __nv_bfloat16* __restrict__ CH, __nv_bfloat16* __restrict__ CL,
    int M)
{
    __shared__ __nv_bfloat16 AsH[128][40], AsL[128][40], BsH[128][40], BsL[128][40];
    const int tid = threadIdx.x;
    const int wid = tid >> 5, lane = tid & 31;
    const int wm = wid & 3, wn = wid >> 2;
    const int m0 = blockIdx.y * 128, n0 = blockIdx.x * 128;
    const int a_r = lane & 15, a_c = (lane >> 4) * 8;
    const int b_r = lane & 7,  b_c = (lane >> 3) * 8;

    float acc[2][8][4];
#pragma unroll
    for (int mi = 0; mi < 2; mi++)
#pragma unroll
        for (int ni = 0; ni < 8; ni++)
#pragma unroll
            for (int r = 0; r < 4; r++) acc[mi][ni][r] = 0.f;

    for (int chunk = 0; chunk < 16; chunk++) {
        const int k0 = chunk * 32;
        __syncthreads();
#pragma unroll
        for (int i = 0; i < 2; i++) {
            const int s = tid + 256 * i;
            const int row = s >> 2, cs = (s & 3) * 8;
            const int gr = m0 + row;
            uint4 z = make_uint4(0, 0, 0, 0);
            uint4 ahv = z, alv = z;
            if (gr < M) {
                size_t off = (size_t)gr * 512 + k0 + cs;
                ahv = *(const uint4*)(AH + off);
                alv = *(const uint4*)(AL + off);
            }
            size_t woff = (size_t)(n0 + row) * 512 + k0 + cs;
            uint4 whv = *(const uint4*)(WH + woff);
            uint4 wlv = *(const uint4*)(WL + woff);
            *(uint2*)&AsH[row][cs]     = make_uint2(ahv.x, ahv.y);
            *(uint2*)&AsH[row][cs + 4] = make_uint2(ahv.z, ahv.w);
            *(uint2*)&AsL[row][cs]     = make_uint2(alv.x, alv.y);
            *(uint2*)&AsL[row][cs + 4] = make_uint2(alv.z, alv.w);
            *(uint2*)&BsH[row][cs]     = make_uint2(whv.x, whv.y);
            *(uint2*)&BsH[row][cs + 4] = make_uint2(whv.z, whv.w);
            *(uint2*)&BsL[row][cs]     = make_uint2(wlv.x, wlv.y);
            *(uint2*)&BsL[row][cs + 4] = make_uint2(wlv.z, wlv.w);
        }
        __syncthreads();

        uint32_t ah[2][2][4], al[2][2][4];
#pragma unroll
        for (int mi = 0; mi < 2; mi++) {
            const int r = wm * 32 + mi * 16 + a_r;
#pragma unroll
            for (int ks = 0; ks < 2; ks++) {
                const int c = ks * 16 + a_c;
                ldsm_x4(ah[mi][ks], smem_addr(&AsH[r][c]));
                ldsm_x4(al[mi][ks], smem_addr(&AsL[r][c]));
            }
        }
#pragma unroll
        for (int ni = 0; ni < 8; ni++) {
            const int r = wn * 64 + ni * 8 + b_r;
            uint32_t bh4[4], bl4[4];
            ldsm_x4(bh4, smem_addr(&BsH[r][b_c]));
            ldsm_x4(bl4, smem_addr(&BsL[r][b_c]));
#pragma unroll
            for (int mi = 0; mi < 2; mi++) {
#pragma unroll
                for (int ks = 0; ks < 2; ks++) {
                    mma_bf16(acc[mi][ni], ah[mi][ks], bh4[2 * ks], bh4[2 * ks + 1]);
                    mma_bf16(acc[mi][ni], ah[mi][ks], bl4[2 * ks], bl4[2 * ks + 1]);
                    mma_bf16(acc[mi][ni], al[mi][ks], bh4[2 * ks], bh4[2 * ks + 1]);
                }
            }
        }
    }

    const int tr = lane >> 2, tc = (lane & 3) * 2;
#pragma unroll
    for (int mi = 0; mi < 2; mi++) {
#pragma unroll
        for (int ni = 0; ni < 8; ni++) {
            const int n = n0 + wn * 64 + ni * 8 + tc;
            const float b0 = bias[n], b1 = bias[n + 1];
            float s0 = 1.f, s1 = 1.f;
            if (scale) { s0 = scale[n]; s1 = scale[n + 1]; }
#pragma unroll
            for (int half = 0; half < 2; half++) {
                const int m = m0 + wm * 32 + mi * 16 + tr + half * 8;
                if (m >= M) continue;
                const float x = (acc[mi][ni][half * 2 + 0] + b0) * s0;
                const float y = (acc[mi][ni][half * 2 + 1] + b1) * s1;
                const size_t off = (size_t)m * 512 + n;
                if (Cf) *(float2*)(Cf + off) = make_float2(x, y);
                if (CH) {
                    uint32_t hi, lo; split2(x, y, hi, lo);
                    *(uint32_t*)(CH + off) = hi;
                    *(uint32_t*)(CL + off) = lo;
                }
            }
        }
    }
}

// ================= gather + normalize (warp per row) =================
__global__ void gather_kernel2(const float* __restrict__ colh, const float* __restrict__ colt,
                               const int* __restrict__ ids)
{
    const int w = (blockIdx.x * blockDim.x + threadIdx.x) >> 5;
    const int lane = threadIdx.x & 31;
    if (w >= BHT) return;
    const int q = w % T;
    const int bh = w / T;
    const int h = bh & 7, b = bh >> 3;
    const int srow = (q == 0) ? 0 : (ids[b * (T - 1) + (q - 1)] + 1);

    {
        float v = (lane < 22) ? colh[((size_t)h * NCOLS + srow) * 22 + lane] : 0.f;
        float ss = v * v;
#pragma unroll
        for (int o = 16; o; o >>= 1) ss += __shfl_xor_sync(0xffffffffu, ss, o);
        float nv = (lane < 22) ? v / sqrtf(ss) : 0.f;
        if (lane < 24) g_chf[(size_t)w * 24 + lane] = nv;
        __nv_bfloat16 hi = __float2bfloat16_rn(nv);
        float lo = nv - __bfloat162float(hi);
        g_chH[(size_t)w * 32 + lane] = hi;
        g_chL[(size_t)w * 32 + lane] = __float2bfloat16_rn(lo);
    }
    {
        float v = (lane < 22) ? colt[((size_t)h * NCOLS + srow) * 22 + lane] : 0.f;
        float ss = v * v;
#pragma unroll
        for (int o = 16; o; o >>= 1) ss += __shfl_xor_sync(0xffffffffu, ss, o);
        float nv = (lane < 22) ? v / sqrtf(ss) : 0.f;
        if (lane < 24) g_ctf[(size_t)w * 24 + lane] = nv;
        __nv_bfloat16 hi = __float2bfloat16_rn(nv);
        float lo = nv - __bfloat162float(hi);
        g_ctH[(size_t)w * 32 + lane] = hi;
        g_ctL[(size_t)w * 32 + lane] = __float2bfloat16_rn(lo);
    }
}

// ================= logits: HMMA phase A (adjacency) + phase B (scores) =================
constexpr uint32_t LOGITS_SMEM = 4 * 128 * 72 * 2;   // 73728

__global__ __launch_bounds__(256) void logits_hmma(const float* __restrict__ bias,
                                                   float* __restrict__ FR)
{
    extern __shared__ char dsm[];
    typedef __nv_bfloat16 row40[40];
    typedef __nv_bfloat16 row72[72];

    const int tid = threadIdx.x;
    const int wid = tid >> 5, lane = tid & 31;
    const int wm = wid & 3, wn = wid >> 2;
    const int bh = blockIdx.z, b = bh >> 3, h = bh & 7;
    const int q0 = blockIdx.y * 128, k0 = blockIdx.x * 128;
    const int a_r = lane & 15, a_c = (lane >> 4) * 8;
    const int b_r = lane & 7,  b_c = (lane >> 3) * 8;
    const int tr = lane >> 2,  tc = (lane & 3) * 2;
    const float bias0 = bias[0];

    float acc[2][8][4];
#pragma unroll
    for (int mi = 0; mi < 2; mi++)
#pragma unroll
        for (int ni = 0; ni < 8; ni++)
#pragma unroll
            for (int r = 0; r < 4; r++) acc[mi][ni][r] = 0.f;

    // ---- phase A: adjacency scores (22-d, padded 32) ----
    {
        row40* QH = (row40*)(dsm);
        row40* QL = (row40*)(dsm + 10240);
        row40* KH = (row40*)(dsm + 20480);
        row40* KL = (row40*)(dsm + 30720);
#pragma unroll
        for (int i = 0; i < 2; i++) {
            const int s = tid + 256 * i;
            const int row = s >> 2, cs = (s & 3) * 8;
            uint4 z = make_uint4(0, 0, 0, 0);
            uint4 qh = z, ql = z, kh = z, kl = z;
            const int q = q0 + row;
            if (q < T) {
                size_t off = ((size_t)bh * T + q) * 32 + cs;
                qh = *(const uint4*)(g_chH + off);
                ql = *(const uint4*)(g_chL + off);
            }
            const int k = k0 + row;
            if (k < T) {
                size_t off = ((size_t)bh * T + k) * 32 + cs;
                kh = *(const uint4*)(g_ctH + off);
                kl = *(const uint4*)(g_ctL + off);
            }
            *(uint2*)&QH[row][cs]     = make_uint2(qh.x, qh.y);
            *(uint2*)&QH[row][cs + 4] = make_uint2(qh.z, qh.w);
            *(uint2*)&QL[row][cs]     = make_uint2(ql.x, ql.y);
            *(uint2*)&QL[row][cs + 4] = make_uint2(ql.z, ql.w);
            *(uint2*)&KH[row][cs]     = make_uint2(kh.x, kh.y);
            *(uint2*)&KH[row][cs + 4] = make_uint2(kh.z, kh.w);
            *(uint2*)&KL[row][cs]     = make_uint2(kl.x, kl.y);
            *(uint2*)&KL[row][cs + 4] = make_uint2(kl.z, kl.w);
        }
        __syncthreads();

        uint32_t ah[2][2][4], al[2][2][4];
#pragma unroll
        for (int mi = 0; mi < 2; mi++) {
            const int r = wm * 32 + mi * 16 + a_r;
#pragma unroll
            for (int ks = 0; ks < 2; ks++) {
                const int c = ks * 16 + a_c;
                ldsm_x4(ah[mi][ks], smem_addr(&QH[r][c]));
                ldsm_x4(al[mi][ks], smem_addr(&QL[r][c]));
            }
        }
#pragma unroll
        for (int ni = 0; ni < 8; ni++) {
            const int r = wn * 64 + ni * 8 + b_r;
            uint32_t bh4[4], bl4[4];
            ldsm_x4(bh4, smem_addr(&KH[r][b_c]));
            ldsm_x4(bl4, smem_addr(&KL[r][b_c]));
#pragma unroll
            for (int mi = 0; mi < 2; mi++) {
#pragma unroll
                for (int ks = 0; ks < 2; ks++) {
                    mma_bf16(acc[mi][ni], ah[mi][ks], bh4[2 * ks], bh4[2 * ks + 1]);
                    mma_bf16(acc[mi][ni], ah[mi][ks], bl4[2 * ks], bl4[2 * ks + 1]);
                    mma_bf16(acc[mi][ni], al[mi][ks], bh4[2 * ks], bh4[2 * ks + 1]);
                }
            }
        }
    }

    unsigned long long adjm = 0ull, unc = 0ull;
#pragma unroll
    for (int mi = 0; mi < 2; mi++)
#pragma unroll
        for (int ni = 0; ni < 8; ni++)
#pragma unroll
            for (int r = 0; r < 4; r++) {
                const int q = q0 + wm * 32 + mi * 16 + tr + (r >> 1) * 8;
                const int k = k0 + wn * 64 + ni * 8 + tc + (r & 1);
                const bool valid = (q < T) && (k < T) && (k != 0) && (k != q);
                if (valid) {
                    const float ts = acc[mi][ni][r] + bias0;
                    const int idx = (mi * 8 + ni) * 4 + r;
                    if (fabsf(ts) < 1e-4f) unc  |= 1ull << idx;
                    if (ts > 0.f)          adjm |= 1ull << idx;
                }
            }

    // ---- phase B: weight scores (64-d) ----
#pragma unroll
    for (int mi = 0; mi < 2; mi++)
#pragma unroll
        for (int ni = 0; ni < 8; ni++)
#pragma unroll
            for (int r = 0; r < 4; r++) acc[mi][ni][r] = 0.f;
    __syncthreads();
    {
        row72* XH = (row72*)(dsm);
        row72* XL = (row72*)(dsm + 18432);
        row72* YH = (row72*)(dsm + 36864);
        row72* YL = (row72*)(dsm + 55296);
#pragma unroll
        for (int i = 0; i < 4; i++) {
            const int s = tid + 256 * i;
            const int row = s >> 3, cs = (s & 7) * 8;
            uint4 z = make_uint4(0, 0, 0, 0);
            uint4 xh = z, xl = z, yh = z, yl = z;
            const int q = q0 + row;
            if (q < T) {
                size_t off = ((size_t)(b * T + q)) * 512 + h * 64 + cs;
                xh = *(const uint4*)(g_fhH + off);
                xl = *(const uint4*)(g_fhL + off);
            }
            const int k = k0 + row;
            if (k < T) {
                size_t off = ((size_t)(b * T + k)) * 512 + h * 64 + cs;
                yh = *(const uint4*)(g_ftH + off);
                yl = *(const uint4*)(g_ftL + off);
            }
            *(uint4*)&XH[row][cs] = xh;
            *(uint4*)&XL[row][cs] = xl;
            *(uint4*)&YH[row][cs] = yh;
            *(uint4*)&YL[row][cs] = yl;
        }
        __syncthreads();

#pragma unroll
        for (int kk = 0; kk < 64; kk += 32) {
            uint32_t ah[2][2][4], al[2][2][4];
#pragma unroll
            for (int mi = 0; mi < 2; mi++) {
                const int r = wm * 32 + mi * 16 + a_r;
#pragma unroll
                for (int ks = 0; ks < 2; ks++) {
                    const int c = kk + ks * 16 + a_c;
                    ldsm_x4(ah[mi][ks], smem_addr(&XH[r][c]));
                    ldsm_x4(al[mi][ks], smem_addr(&XL[r][c]));
                }
            }
#pragma unroll
            for (int ni = 0; ni < 8; ni++) {
                const int r = wn * 64 + ni * 8 + b_r;
                uint32_t bh4[4], bl4[4];
                ldsm_x4(bh4, smem_addr(&YH[r][kk + b_c]));
                ldsm_x4(bl4, smem_addr(&YL[r][kk + b_c]));
#pragma unroll
                for (int mi = 0; mi < 2; mi++) {
#pragma unroll
                    for (int ks = 0; ks < 2; ks++) {
                        mma_bf16(acc[mi][ni], ah[mi][ks], bh4[2 * ks], bh4[2 * ks + 1]);
                        mma_bf16(acc[mi][ni], ah[mi][ks], bl4[2 * ks], bl4[2 * ks + 1]);
                        mma_bf16(acc[mi][ni], al[mi][ks], bh4[2 * ks], bh4[2 * ks + 1]);
                    }
                }
            }
        }
    }

    // ---- epilogue ----
#pragma unroll
    for (int mi = 0; mi < 2; mi++) {
#pragma unroll
        for (int ni = 0; ni < 8; ni++) {
#pragma unroll
            for (int r = 0; r < 4; r++) {
                const int q = q0 + wm * 32 + mi * 16 + tr + (r >> 1) * 8;
                const int k = k0 + wn * 64 + ni * 8 + tc + (r & 1);
                if (q >= T || k >= T) continue;
                const int idx = (mi * 8 + ni) * 4 + r;
                bool abit;
                if ((unc >> idx) & 1ull) {
                    const float* cq = g_chf + ((size_t)bh * T + q) * 24;
                    const float* ck = g_ctf + ((size_t)bh * T + k) * 24;
                    float d = 0.f;
#pragma unroll
                    for (int c = 0; c < 22; c++) d = fmaf(cq[c], ck[c], d);
                    abit = (d + bias0 > 0.f);
                } else {
                    abit = (adjm >> idx) & 1ull;
                }
                float v = acc[mi][ni][r] * 0.125f;
                if (!abit) v -= 10000.0f;
                FR[((size_t)bh * T + q) * T + k] = v;
            }
        }
    }
}

// ================= softmax: in-place, also emits padded bf16 hi/lo P planes =================
__global__ __launch_bounds__(256) void softmax_kernel(float* __restrict__ FR)
{
    __shared__ float sred[8];
    const int tid = threadIdx.x;
    const int wid = tid >> 5, lane = tid & 31;
    float* base = FR + (size_t)blockIdx.x * T;
    __nv_bfloat16* ph = g_pH + (size_t)blockIdx.x * TP;
    __nv_bfloat16* pl = g_pL + (size_t)blockIdx.x * TP;

    float v[4];
    int n = 0;
    float m = -3.0e38f;
    for (int i = tid; i < T; i += 256) { v[n] = base[i]; m = fmaxf(m, v[n]); n++; }
#pragma unroll
    for (int o = 16; o; o >>= 1) m = fmaxf(m, __shfl_xor_sync(0xffffffffu, m, o));
    if (lane == 0) sred[wid] = m;
    __syncthreads();
    m = sred[0];
#pragma unroll
    for (int w = 1; w < 8; w++) m = fmaxf(m, sred[w]);
    __syncthreads();

    float e[4];
    float s = 0.f;
    for (int i = 0; i < n; i++) { e[i] = expf(v[i] - m); s += e[i]; }
#pragma unroll
    for (int o = 16; o; o >>= 1) s += __shfl_xor_sync(0xffffffffu, s, o);
    if (lane == 0) sred[wid] = s;
    __syncthreads();
    s = 0.f;
#pragma unroll
    for (int w = 0; w < 8; w++) s += sred[w];
    float inv = 1.0f / s;
    n = 0;
    for (int i = tid; i < T; i += 256) {
        const float p = e[n] * inv;
        base[i] = p;
        const __nv_bfloat16 hi = __float2bfloat16_rn(p);
        ph[i] = hi;
        pl[i] = __float2bfloat16_rn(p - __bfloat162float(hi));
        n++;
    }
}

// ================= AV on HMMA: xatt = P @ V from padded bf16 planes =================
__global__ __launch_bounds__(256) void av_hmma()
{
    __shared__ __nv_bfloat16 PsH[128][40], PsL[128][40];
    __shared__ __nv_bfloat16 VsH[32][72], VsL[32][72];
    const int tid = threadIdx.x;
    const int wid = tid >> 5, lane = tid & 31;
    const int wm = wid & 3, wn = wid >> 2;
    const int bh = blockIdx.y, b = bh >> 3, h = bh & 7;
    const int q0 = blockIdx.x * 128;
    const int a_r = lane & 15, a_c = (lane >> 4) * 8;
    const int tr = lane >> 2, tc = (lane & 3) * 2;

    float acc[2][4][4];
#pragma unroll
    for (int mi = 0; mi < 2; mi++)
#pragma unroll
        for (int ni = 0; ni < 4; ni++)
#pragma unroll
            for (int r = 0; r < 4; r++) acc[mi][ni][r] = 0.f;

    for (int k0 = 0; k0 < TP; k0 += 32) {
        __syncthreads();
        // P tile: 128 x 32 bf16 planes (padded rows; pad cols are zero)
#pragma unroll
        for (int i = 0; i < 2; i++) {
            const int s = tid + 256 * i;
            const int row = s >> 2, c8 = (s & 3) * 8;
            const int q = q0 + row;
            uint4 hv = make_uint4(0, 0, 0, 0), lv = hv;
            if (q < T) {
                const size_t off = ((size_t)bh * T + q) * TP + k0 + c8;
                hv = *(const uint4*)(g_pH + off);
                lv = *(const uint4*)(g_pL + off);
            }
            *(uint4*)&PsH[row][c8] = hv;
            *(uint4*)&PsL[row][c8] = lv;
        }
        // V tile: 32 x 64 bf16 planes
        {
            const int row = tid >> 3, c8 = (tid & 7) * 8;
            const int kv = k0 + row;
            uint4 vh = make_uint4(0, 0, 0, 0), vl = vh;
            if (kv < T) {
                size_t off = ((size_t)(b * T + kv)) * 512 + h * 64 + c8;
                vh = *(const uint4*)(g_fvH + off);
                vl = *(const uint4*)(g_fvL + off);
            }
            *(uint4*)&VsH[row][c8] = vh;
            *(uint4*)&VsL[row][c8] = vl;
        }
        __syncthreads();

        uint32_t ah[2][2][4], al[2][2][4];
#pragma unroll
        for (int mi = 0; mi < 2; mi++) {
            const int r = wm * 32 + mi * 16 + a_r;
#pragma unroll
            for (int ks = 0; ks < 2; ks++) {
                const int c = ks * 16 + a_c;
                ldsm_x4(ah[mi][ks], smem_addr(&PsH[r][c]));
                ldsm_x4(al[mi][ks], smem_addr(&PsL[r][c]));
            }
        }
#pragma unroll
        for (int ni = 0; ni < 4; ni++) {
            const int nb = wn * 32 + ni * 8;
            uint32_t bh4[4], bl4[4];
            ldsm_x4_t(bh4, smem_addr(&VsH[lane][nb]));
            ldsm_x4_t(bl4, smem_addr(&VsL[lane][nb]));
#pragma unroll
            for (int mi = 0; mi < 2; mi++) {
#pragma unroll
                for (int ks = 0; ks < 2; ks++) {
                    mma_bf16(acc[mi][ni], ah[mi][ks], bh4[2 * ks], bh4[2 * ks + 1]);
                    mma_bf16(acc[mi][ni], ah[mi][ks], bl4[2 * ks], bl4[2 * ks + 1]);
                    mma_bf16(acc[mi][ni], al[mi][ks], bh4[2 * ks], bh4[2 * ks + 1]);
                }
            }
        }
    }

#pragma unroll
    for (int mi = 0; mi < 2; mi++) {
#pragma unroll
        for (int ni = 0; ni < 4; ni++) {
            const int n = wn * 32 + ni * 8 + tc;
#pragma unroll
            for (int half = 0; half < 2; half++) {
                const int q = q0 + wm * 32 + mi * 16 + tr + half * 8;
                if (q >= T) continue;
                const float x = acc[mi][ni][half * 2 + 0];
                const float y = acc[mi][ni][half * 2 + 1];
                uint32_t hi, lo; split2(x, y, hi, lo);
                const size_t off = ((size_t)(b * T + q)) * 512 + h * 64 + n;
                *(uint32_t*)(g_xaH + off) = hi;
                *(uint32_t*)(g_xaL + off) = lo;
            }
        }
    }
}

// ---------------- launcher ----------------
extern "C" void kernel_launch(void* const* d_in, const int* in_sizes, int n_in,
                              void* d_out, int out_size)
{
    const float* x_head = (const float*)d_in[0];
    const float* x_tail = (const float*)d_in[1];
    const int*   ids    = (const int*)  d_in[2];
    const float* Wh     = (const float*)d_in[3];
    const float* bh     = (const float*)d_in[4];
    const float* Wv     = (const float*)d_in[5];
    const float* bv     = (const float*)d_in[6];
    const float* Wo     = (const float*)d_in[7];
    const float* bo     = (const float*)d_in[8];
    const float* rel    = (const float*)d_in[9];
    const float* colh   = (const float*)d_in[10];
    const float* colt   = (const float*)d_in[11];
    const float* bias   = (const float*)d_in[12];

    float* out = (float*)d_out;
    float* FR  = out + X_ELEMS;

    __nv_bfloat16 *xhH, *xhL, *xtH, *xtL, *WhH, *WhL, *WvH, *WvL, *WoH, *WoL;
    __nv_bfloat16 *fhH, *fhL, *ftH, *ftL, *fvH, *fvL, *xaH, *xaL;
    cudaGetSymbolAddress((void**)&xhH, g_xhH); cudaGetSymbolAddress((void**)&xhL, g_xhL);
    cudaGetSymbolAddress((void**)&xtH, g_xtH); cudaGetSymbolAddress((void**)&xtL, g_xtL);
    cudaGetSymbolAddress((void**)&WhH, g_WhH); cudaGetSymbolAddress((void**)&WhL, g_WhL);
    cudaGetSymbolAddress((void**)&WvH, g_WvH); cudaGetSymbolAddress((void**)&WvL, g_WvL);
    cudaGetSymbolAddress((void**)&WoH, g_WoH); cudaGetSymbolAddress((void**)&WoL, g_WoL);
    cudaGetSymbolAddress((void**)&fhH, g_fhH); cudaGetSymbolAddress((void**)&fhL, g_fhL);
    cudaGetSymbolAddress((void**)&ftH, g_ftH); cudaGetSymbolAddress((void**)&ftL, g_ftL);
    cudaGetSymbolAddress((void**)&fvH, g_fvH); cudaGetSymbolAddress((void**)&fvL, g_fvL);
    cudaGetSymbolAddress((void**)&xaH, g_xaH); cudaGetSymbolAddress((void**)&xaL, g_xaL);

    cudaFuncSetAttribute(logits_hmma, cudaFuncAttributeMaxDynamicSharedMemorySize, LOGITS_SMEM);

    const int nx4 = BT * 512 / 4, nw4 = 512 * 512 / 4;
    convert_kernel<<<(nx4 + 255) / 256, 256>>>(x_head, xhH, xhL, nx4);
    convert_kernel<<<(nx4 + 255) / 256, 256>>>(x_tail, xtH, xtL, nx4);
    convert_kernel<<<(nw4 + 255) / 256, 256>>>(Wh, WhH, WhL, nw4);
    convert_kernel<<<(nw4 + 255) / 256, 256>>>(Wv, WvH, WvL, nw4);
    convert_kernel<<<(nw4 + 255) / 256, 256>>>(Wo, WoH, WoL, nw4);

    dim3 gProj(4, (BT + 127) / 128);
    gemm_hmma2<<<gProj, 256>>>(xhH, xhL, WhH, WhL, bh, rel,     nullptr, fhH, fhL, BT);
    gemm_hmma2<<<gProj, 256>>>(xtH, xtL, WhH, WhL, bh, nullptr, nullptr, ftH, ftL, BT);
    gemm_hmma2<<<gProj, 256>>>(xtH, xtL, WvH, WvL, bv, nullptr, nullptr, fvH, fvL, BT);

    gather_kernel2<<<(BHT * 32 + 255) / 256, 256>>>(colh, colt, ids);

    dim3 gLog((T + 127) / 128, (T + 127) / 128, B * H);
    logits_hmma<<<gLog, 256, LOGITS_SMEM>>>(bias, FR);

    softmax_kernel<<<B * H * T, 256>>>(FR);

    dim3 gAV((T + 127) / 128, B * H);
    av_hmma<<<gAV, 256>>>();

    gemm_hmma2<<<gProj, 256>>>(xaH, xaL, WoH, WoL, bo, nullptr, out, nullptr, nullptr, BT);
}

// round 6
// speedup vs baseline: 1.5865x; 1.1967x over previous
#include <cuda_runtime.h>
#include <cuda_bf16.h>
#include <math.h>
#include <stdint.h>

// ---------------- problem constants ----------------
constexpr int B = 8;
constexpr int T = 769;
constexpr int H = 8;
constexpr int NCOLS = 2048;
constexpr int BT = B * T;            // 6152
constexpr int BHT = B * H * T;       // 49216
constexpr int TP = 800;              // padded T for P planes
constexpr long long X_ELEMS = (long long)BT * 512;

typedef __nv_bfloat16 bf16;

// ---------------- scratch (device globals; zero-initialized) ----------------
__device__ bf16 g_xhH[BT * 512], g_xhL[BT * 512];
__device__ bf16 g_xtH[BT * 512], g_xtL[BT * 512];
__device__ bf16 g_WhH[512 * 512], g_WhL[512 * 512];
__device__ bf16 g_WvH[512 * 512], g_WvL[512 * 512];
__device__ bf16 g_WoH[512 * 512], g_WoL[512 * 512];
__device__ bf16 g_fhH[BT * 512], g_fhL[BT * 512];
__device__ bf16 g_ftH[BT * 512], g_ftL[BT * 512];
__device__ bf16 g_fvH[BT * 512], g_fvL[BT * 512];
__device__ bf16 g_xaH[BT * 512], g_xaL[BT * 512];
__device__ bf16 g_chH[BHT * 32], g_chL[BHT * 32];
__device__ bf16 g_ctH[BHT * 32], g_ctL[BHT * 32];
__device__ float g_chf[BHT * 24], g_ctf[BHT * 24];
__device__ bf16 g_pH[(size_t)BHT * TP], g_pL[(size_t)BHT * TP];

// ================= helpers =================
__device__ __forceinline__ void ldsm_x4(uint32_t* r, uint32_t addr) {
    asm volatile("ldmatrix.sync.aligned.m8n8.x4.shared.b16 {%0,%1,%2,%3}, [%4];"
                 : "=r"(r[0]), "=r"(r[1]), "=r"(r[2]), "=r"(r[3]) : "r"(addr));
}
__device__ __forceinline__ void ldsm_x4_t(uint32_t* r, uint32_t addr) {
    asm volatile("ldmatrix.sync.aligned.m8n8.x4.trans.shared.b16 {%0,%1,%2,%3}, [%4];"
                 : "=r"(r[0]), "=r"(r[1]), "=r"(r[2]), "=r"(r[3]) : "r"(addr));
}
__device__ __forceinline__ void mma_bf16(float* c, const uint32_t* a, uint32_t b0, uint32_t b1) {
    asm volatile("mma.sync.aligned.m16n8k16.row.col.f32.bf16.bf16.f32 "
                 "{%0,%1,%2,%3}, {%4,%5,%6,%7}, {%8,%9}, {%0,%1,%2,%3};"
                 : "+f"(c[0]), "+f"(c[1]), "+f"(c[2]), "+f"(c[3])
                 : "r"(a[0]), "r"(a[1]), "r"(a[2]), "r"(a[3]), "r"(b0), "r"(b1));
}
__device__ __forceinline__ uint32_t smem_addr(const void* p) {
    return (uint32_t)__cvta_generic_to_shared(p);
}
__device__ __forceinline__ void cp16(uint32_t dst, const void* src, int bytes) {
    asm volatile("cp.async.cg.shared.global [%0], [%1], 16, %2;"
                 :: "r"(dst), "l"(src), "r"(bytes));
}
#define CP_COMMIT() asm volatile("cp.async.commit_group;")
#define CP_WAIT(n)  asm volatile("cp.async.wait_group %0;" :: "n"(n))

__device__ __forceinline__ void split4(float4 v, uint2& hi, uint2& lo) {
    float f[4] = {v.x, v.y, v.z, v.w};
    float fh[4], fl[4];
#pragma unroll
    for (int j = 0; j < 4; j++) {
        fh[j] = __bfloat162float(__float2bfloat16_rn(f[j]));
        fl[j] = f[j] - fh[j];
    }
    union { __nv_bfloat162 h2[2]; uint2 u; } a, b;
    a.h2[0] = __floats2bfloat162_rn(fh[0], fh[1]);
    a.h2[1] = __floats2bfloat162_rn(fh[2], fh[3]);
    b.h2[0] = __floats2bfloat162_rn(fl[0], fl[1]);
    b.h2[1] = __floats2bfloat162_rn(fl[2], fl[3]);
    hi = a.u; lo = b.u;
}
__device__ __forceinline__ void split2(float x, float y, uint32_t& hi, uint32_t& lo) {
    float hx = __bfloat162float(__float2bfloat16_rn(x));
    float hy = __bfloat162float(__float2bfloat16_rn(y));
    union { __nv_bfloat162 h2; uint32_t u; } a, b;
    a.h2 = __floats2bfloat162_rn(hx, hy);
    b.h2 = __floats2bfloat162_rn(x - hx, y - hy);
    hi = a.u; lo = b.u;
}

// ================= converts =================
__global__ void convert_kernel(const float* __restrict__ in,
                               bf16* __restrict__ hi, bf16* __restrict__ lo, int n4)
{
    int i = blockIdx.x * blockDim.x + threadIdx.x;
    if (i >= n4) return;
    float4 v = ((const float4*)in)[i];
    uint2 h, l; split4(v, h, l);
    ((uint2*)hi)[i] = h;
    ((uint2*)lo)[i] = l;
}
__global__ void convert_w3_kernel(const float* __restrict__ w0, const float* __restrict__ w1,
                                  const float* __restrict__ w2,
                                  bf16* h0, bf16* l0, bf16* h1, bf16* l1, bf16* h2, bf16* l2)
{
    const int n4 = 512 * 512 / 4;
    int i = blockIdx.x * blockDim.x + threadIdx.x;
    if (i >= n4) return;
    const float* in = (blockIdx.y == 0) ? w0 : (blockIdx.y == 1) ? w1 : w2;
    bf16* hi = (blockIdx.y == 0) ? h0 : (blockIdx.y == 1) ? h1 : h2;
    bf16* lo = (blockIdx.y == 0) ? l0 : (blockIdx.y == 1) ? l1 : l2;
    float4 v = ((const float4*)in)[i];
    uint2 h, l; split4(v, h, l);
    ((uint2*)hi)[i] = h;
    ((uint2*)lo)[i] = l;
}

// ================= batched pipelined HMMA GEMM =================
struct Job {
    const bf16 *AH, *AL, *WH, *WL;
    const float *bias, *scale;
    float* Cf;
    bf16 *CH, *CL;
};
struct Jobs3 { Job j[3]; };

// dynamic smem: 2 stages x 4 planes x 128 x 40 bf16 = 81920 B
constexpr uint32_t GEMM_SMEM = 2 * 4 * 128 * 40 * 2;
constexpr uint32_t G_PL = 128 * 40 * 2;   // plane stride 10240
constexpr uint32_t G_ST = 4 * G_PL;       // stage stride 40960

__global__ __launch_bounds__(256) void gemm_batched(Jobs3 jobs, int M)
{
    extern __shared__ char dsm[];
    const Job J = jobs.j[blockIdx.z];
    const uint32_t sm = smem_addr(dsm);
    const int tid = threadIdx.x;
    const int wid = tid >> 5, lane = tid & 31;
    const int wm = wid & 3, wn = wid >> 2;
    const int m0 = blockIdx.y * 128, n0 = blockIdx.x * 128;
    const int a_r = lane & 15, a_c = (lane >> 4) * 8;
    const int b_r = lane & 7,  b_c = (lane >> 3) * 8;

    float acc[2][8][4];
#pragma unroll
    for (int mi = 0; mi < 2; mi++)
#pragma unroll
        for (int ni = 0; ni < 8; ni++)
#pragma unroll
            for (int r = 0; r < 4; r++) acc[mi][ni][r] = 0.f;

    // per-thread load coords: s in [0,512): row = s>>2, cs = (s&3)*8
    const int r0 = tid >> 2, c0 = (tid & 3) * 8;
    const int r1 = (tid + 256) >> 2, c1 = ((tid + 256) & 3) * 8;

    auto load_stage = [&](int st, int chunk) {
        const int k0 = chunk * 32;
        const uint32_t base = sm + st * G_ST;
#pragma unroll
        for (int i = 0; i < 2; i++) {
            const int row = i ? r1 : r0, cs = i ? c1 : c0;
            const int gr = m0 + row;
            const int grc = (gr < M) ? gr : (M - 1);
            const int ab = (gr < M) ? 16 : 0;
            const size_t aoff = (size_t)grc * 512 + k0 + cs;
            const size_t woff = (size_t)(n0 + row) * 512 + k0 + cs;
            const uint32_t so = (row * 40 + cs) * 2;
            cp16(base + so,            J.AH + aoff, ab);
            cp16(base + G_PL + so,     J.AL + aoff, ab);
            cp16(base + 2 * G_PL + so, J.WH + woff, 16);
            cp16(base + 3 * G_PL + so, J.WL + woff, 16);
        }
    };

    load_stage(0, 0);
    CP_COMMIT();

    for (int chunk = 0; chunk < 16; chunk++) {
        const int st = chunk & 1;
        if (chunk + 1 < 16) {
            load_stage(st ^ 1, chunk + 1);
            CP_COMMIT();
            CP_WAIT(1);
        } else {
            CP_WAIT(0);
        }
        __syncthreads();

        bf16 (*AsH)[40] = (bf16(*)[40])(dsm + st * G_ST);
        bf16 (*AsL)[40] = (bf16(*)[40])(dsm + st * G_ST + G_PL);
        bf16 (*BsH)[40] = (bf16(*)[40])(dsm + st * G_ST + 2 * G_PL);
        bf16 (*BsL)[40] = (bf16(*)[40])(dsm + st * G_ST + 3 * G_PL);

        uint32_t ah[2][2][4], al[2][2][4];
#pragma unroll
        for (int mi = 0; mi < 2; mi++) {
            const int r = wm * 32 + mi * 16 + a_r;
#pragma unroll
            for (int ks = 0; ks < 2; ks++) {
                const int c = ks * 16 + a_c;
                ldsm_x4(ah[mi][ks], smem_addr(&AsH[r][c]));
                ldsm_x4(al[mi][ks], smem_addr(&AsL[r][c]));
            }
        }
#pragma unroll
        for (int ni = 0; ni < 8; ni++) {
            const int r = wn * 64 + ni * 8 + b_r;
            uint32_t bh4[4], bl4[4];
            ldsm_x4(bh4, smem_addr(&BsH[r][b_c]));
            ldsm_x4(bl4, smem_addr(&BsL[r][b_c]));
#pragma unroll
            for (int mi = 0; mi < 2; mi++) {
#pragma unroll
                for (int ks = 0; ks < 2; ks++) {
                    mma_bf16(acc[mi][ni], ah[mi][ks], bh4[2 * ks], bh4[2 * ks + 1]);
                    mma_bf16(acc[mi][ni], ah[mi][ks], bl4[2 * ks], bl4[2 * ks + 1]);
                    mma_bf16(acc[mi][ni], al[mi][ks], bh4[2 * ks], bh4[2 * ks + 1]);
                }
            }
        }
        __syncthreads();
    }

    const int tr = lane >> 2, tc = (lane & 3) * 2;
#pragma unroll
    for (int mi = 0; mi < 2; mi++) {
#pragma unroll
        for (int ni = 0; ni < 8; ni++) {
            const int n = n0 + wn * 64 + ni * 8 + tc;
            const float b0 = J.bias[n], b1 = J.bias[n + 1];
            float s0 = 1.f, s1 = 1.f;
            if (J.scale) { s0 = J.scale[n]; s1 = J.scale[n + 1]; }
#pragma unroll
            for (int half = 0; half < 2; half++) {
                const int m = m0 + wm * 32 + mi * 16 + tr + half * 8;
                if (m >= M) continue;
                const float x = (acc[mi][ni][half * 2 + 0] + b0) * s0;
                const float y = (acc[mi][ni][half * 2 + 1] + b1) * s1;
                const size_t off = (size_t)m * 512 + n;
                if (J.Cf) *(float2*)(J.Cf + off) = make_float2(x, y);
                if (J.CH) {
                    uint32_t hi, lo; split2(x, y, hi, lo);
                    *(uint32_t*)(J.CH + off) = hi;
                    *(uint32_t*)(J.CL + off) = lo;
                }
            }
        }
    }
}

// ================= gather + normalize (warp per row) =================
__global__ void gather_kernel2(const float* __restrict__ colh, const float* __restrict__ colt,
                               const int* __restrict__ ids)
{
    const int w = (blockIdx.x * blockDim.x + threadIdx.x) >> 5;
    const int lane = threadIdx.x & 31;
    if (w >= BHT) return;
    const int q = w % T;
    const int bh = w / T;
    const int h = bh & 7, b = bh >> 3;
    const int srow = (q == 0) ? 0 : (ids[b * (T - 1) + (q - 1)] + 1);

    {
        float v = (lane < 22) ? colh[((size_t)h * NCOLS + srow) * 22 + lane] : 0.f;
        float ss = v * v;
#pragma unroll
        for (int o = 16; o; o >>= 1) ss += __shfl_xor_sync(0xffffffffu, ss, o);
        float nv = (lane < 22) ? v / sqrtf(ss) : 0.f;
        if (lane < 24) g_chf[(size_t)w * 24 + lane] = nv;
        bf16 hi = __float2bfloat16_rn(nv);
        float lo = nv - __bfloat162float(hi);
        g_chH[(size_t)w * 32 + lane] = hi;
        g_chL[(size_t)w * 32 + lane] = __float2bfloat16_rn(lo);
    }
    {
        float v = (lane < 22) ? colt[((size_t)h * NCOLS + srow) * 22 + lane] : 0.f;
        float ss = v * v;
#pragma unroll
        for (int o = 16; o; o >>= 1) ss += __shfl_xor_sync(0xffffffffu, ss, o);
        float nv = (lane < 22) ? v / sqrtf(ss) : 0.f;
        if (lane < 24) g_ctf[(size_t)w * 24 + lane] = nv;
        bf16 hi = __float2bfloat16_rn(nv);
        float lo = nv - __bfloat162float(hi);
        g_ctH[(size_t)w * 32 + lane] = hi;
        g_ctL[(size_t)w * 32 + lane] = __float2bfloat16_rn(lo);
    }
}

// ================= logits (unchanged from R5) =================
constexpr uint32_t LOGITS_SMEM = 4 * 128 * 72 * 2;

__global__ __launch_bounds__(256) void logits_hmma(const float* __restrict__ bias,
                                                   float* __restrict__ FR)
{
    extern __shared__ char dsm[];
    typedef bf16 row40[40];
    typedef bf16 row72[72];

    const int tid = threadIdx.x;
    const int wid = tid >> 5, lane = tid & 31;
    const int wm = wid & 3, wn = wid >> 2;
    const int bh = blockIdx.z, b = bh >> 3, h = bh & 7;
    const int q0 = blockIdx.y * 128, k0 = blockIdx.x * 128;
    const int a_r = lane & 15, a_c = (lane >> 4) * 8;
    const int b_r = lane & 7,  b_c = (lane >> 3) * 8;
    const int tr = lane >> 2,  tc = (lane & 3) * 2;
    const float bias0 = bias[0];

    float acc[2][8][4];
#pragma unroll
    for (int mi = 0; mi < 2; mi++)
#pragma unroll
        for (int ni = 0; ni < 8; ni++)
#pragma unroll
            for (int r = 0; r < 4; r++) acc[mi][ni][r] = 0.f;

    {
        row40* QH = (row40*)(dsm);
        row40* QL = (row40*)(dsm + 10240);
        row40* KH = (row40*)(dsm + 20480);
        row40* KL = (row40*)(dsm + 30720);
#pragma unroll
        for (int i = 0; i < 2; i++) {
            const int s = tid + 256 * i;
            const int row = s >> 2, cs = (s & 3) * 8;
            uint4 z = make_uint4(0, 0, 0, 0);
            uint4 qh = z, ql = z, kh = z, kl = z;
            const int q = q0 + row;
            if (q < T) {
                size_t off = ((size_t)bh * T + q) * 32 + cs;
                qh = *(const uint4*)(g_chH + off);
                ql = *(const uint4*)(g_chL + off);
            }
            const int k = k0 + row;
            if (k < T) {
                size_t off = ((size_t)bh * T + k) * 32 + cs;
                kh = *(const uint4*)(g_ctH + off);
                kl = *(const uint4*)(g_ctL + off);
            }
            *(uint2*)&QH[row][cs]     = make_uint2(qh.x, qh.y);
            *(uint2*)&QH[row][cs + 4] = make_uint2(qh.z, qh.w);
            *(uint2*)&QL[row][cs]     = make_uint2(ql.x, ql.y);
            *(uint2*)&QL[row][cs + 4] = make_uint2(ql.z, ql.w);
            *(uint2*)&KH[row][cs]     = make_uint2(kh.x, kh.y);
            *(uint2*)&KH[row][cs + 4] = make_uint2(kh.z, kh.w);
            *(uint2*)&KL[row][cs]     = make_uint2(kl.x, kl.y);
            *(uint2*)&KL[row][cs + 4] = make_uint2(kl.z, kl.w);
        }
        __syncthreads();

        uint32_t ah[2][2][4], al[2][2][4];
#pragma unroll
        for (int mi = 0; mi < 2; mi++) {
            const int r = wm * 32 + mi * 16 + a_r;
#pragma unroll
            for (int ks = 0; ks < 2; ks++) {
                const int c = ks * 16 + a_c;
                ldsm_x4(ah[mi][ks], smem_addr(&QH[r][c]));
                ldsm_x4(al[mi][ks], smem_addr(&QL[r][c]));
            }
        }
#pragma unroll
        for (int ni = 0; ni < 8; ni++) {
            const int r = wn * 64 + ni * 8 + b_r;
            uint32_t bh4[4], bl4[4];
            ldsm_x4(bh4, smem_addr(&KH[r][b_c]));
            ldsm_x4(bl4, smem_addr(&KL[r][b_c]));
#pragma unroll
            for (int mi = 0; mi < 2; mi++) {
#pragma unroll
                for (int ks = 0; ks < 2; ks++) {
                    mma_bf16(acc[mi][ni], ah[mi][ks], bh4[2 * ks], bh4[2 * ks + 1]);
                    mma_bf16(acc[mi][ni], ah[mi][ks], bl4[2 * ks], bl4[2 * ks + 1]);
                    mma_bf16(acc[mi][ni], al[mi][ks], bh4[2 * ks], bh4[2 * ks + 1]);
                }
            }
        }
    }

    unsigned long long adjm = 0ull, unc = 0ull;
#pragma unroll
    for (int mi = 0; mi < 2; mi++)
#pragma unroll
        for (int ni = 0; ni < 8; ni++)
#pragma unroll
            for (int r = 0; r < 4; r++) {
                const int q = q0 + wm * 32 + mi * 16 + tr + (r >> 1) * 8;
                const int k = k0 + wn * 64 + ni * 8 + tc + (r & 1);
                const bool valid = (q < T) && (k < T) && (k != 0) && (k != q);
                if (valid) {
                    const float ts = acc[mi][ni][r] + bias0;
                    const int idx = (mi * 8 + ni) * 4 + r;
                    if (fabsf(ts) < 1e-4f) unc  |= 1ull << idx;
                    if (ts > 0.f)          adjm |= 1ull << idx;
                }
            }

#pragma unroll
    for (int mi = 0; mi < 2; mi++)
#pragma unroll
        for (int ni = 0; ni < 8; ni++)
#pragma unroll
            for (int r = 0; r < 4; r++) acc[mi][ni][r] = 0.f;
    __syncthreads();
    {
        row72* XH = (row72*)(dsm);
        row72* XL = (row72*)(dsm + 18432);
        row72* YH = (row72*)(dsm + 36864);
        row72* YL = (row72*)(dsm + 55296);
#pragma unroll
        for (int i = 0; i < 4; i++) {
            const int s = tid + 256 * i;
            const int row = s >> 3, cs = (s & 7) * 8;
            uint4 z = make_uint4(0, 0, 0, 0);
            uint4 xh = z, xl = z, yh = z, yl = z;
            const int q = q0 + row;
            if (q < T) {
                size_t off = ((size_t)(b * T + q)) * 512 + h * 64 + cs;
                xh = *(const uint4*)(g_fhH + off);
                xl = *(const uint4*)(g_fhL + off);
            }
            const int k = k0 + row;
            if (k < T) {
                size_t off = ((size_t)(b * T + k)) * 512 + h * 64 + cs;
                yh = *(const uint4*)(g_ftH + off);
                yl = *(const uint4*)(g_ftL + off);
            }
            *(uint4*)&XH[row][cs] = xh;
            *(uint4*)&XL[row][cs] = xl;
            *(uint4*)&YH[row][cs] = yh;
            *(uint4*)&YL[row][cs] = yl;
        }
        __syncthreads();

#pragma unroll
        for (int kk = 0; kk < 64; kk += 32) {
            uint32_t ah[2][2][4], al[2][2][4];
#pragma unroll
            for (int mi = 0; mi < 2; mi++) {
                const int r = wm * 32 + mi * 16 + a_r;
#pragma unroll
                for (int ks = 0; ks < 2; ks++) {
                    const int c = kk + ks * 16 + a_c;
                    ldsm_x4(ah[mi][ks], smem_addr(&XH[r][c]));
                    ldsm_x4(al[mi][ks], smem_addr(&XL[r][c]));
                }
            }
#pragma unroll
            for (int ni = 0; ni < 8; ni++) {
                const int r = wn * 64 + ni * 8 + b_r;
                uint32_t bh4[4], bl4[4];
                ldsm_x4(bh4, smem_addr(&YH[r][kk + b_c]));
                ldsm_x4(bl4, smem_addr(&YL[r][kk + b_c]));
#pragma unroll
                for (int mi = 0; mi < 2; mi++) {
#pragma unroll
                    for (int ks = 0; ks < 2; ks++) {
                        mma_bf16(acc[mi][ni], ah[mi][ks], bh4[2 * ks], bh4[2 * ks + 1]);
                        mma_bf16(acc[mi][ni], ah[mi][ks], bl4[2 * ks], bl4[2 * ks + 1]);
                        mma_bf16(acc[mi][ni], al[mi][ks], bh4[2 * ks], bh4[2 * ks + 1]);
                    }
                }
            }
        }
    }

#pragma unroll
    for (int mi = 0; mi < 2; mi++) {
#pragma unroll
        for (int ni = 0; ni < 8; ni++) {
#pragma unroll
            for (int r = 0; r < 4; r++) {
                const int q = q0 + wm * 32 + mi * 16 + tr + (r >> 1) * 8;
                const int k = k0 + wn * 64 + ni * 8 + tc + (r & 1);
                if (q >= T || k >= T) continue;
                const int idx = (mi * 8 + ni) * 4 + r;
                bool abit;
                if ((unc >> idx) & 1ull) {
                    const float* cq = g_chf + ((size_t)bh * T + q) * 24;
                    const float* ck = g_ctf + ((size_t)bh * T + k) * 24;
                    float d = 0.f;
#pragma unroll
                    for (int c = 0; c < 22; c++) d = fmaf(cq[c], ck[c], d);
                    abit = (d + bias0 > 0.f);
                } else {
                    abit = (adjm >> idx) & 1ull;
                }
                float v = acc[mi][ni][r] * 0.125f;
                if (!abit) v -= 10000.0f;
                FR[((size_t)bh * T + q) * T + k] = v;
            }
        }
    }
}

// ================= softmax (unchanged from R5) =================
__global__ __launch_bounds__(256) void softmax_kernel(float* __restrict__ FR)
{
    __shared__ float sred[8];
    const int tid = threadIdx.x;
    const int wid = tid >> 5, lane = tid & 31;
    float* base = FR + (size_t)blockIdx.x * T;
    bf16* ph = g_pH + (size_t)blockIdx.x * TP;
    bf16* pl = g_pL + (size_t)blockIdx.x * TP;

    float v[4];
    int n = 0;
    float m = -3.0e38f;
    for (int i = tid; i < T; i += 256) { v[n] = base[i]; m = fmaxf(m, v[n]); n++; }
#pragma unroll
    for (int o = 16; o; o >>= 1) m = fmaxf(m, __shfl_xor_sync(0xffffffffu, m, o));
    if (lane == 0) sred[wid] = m;
    __syncthreads();
    m = sred[0];
#pragma unroll
    for (int w = 1; w < 8; w++) m = fmaxf(m, sred[w]);
    __syncthreads();

    float e[4];
    float s = 0.f;
    for (int i = 0; i < n; i++) { e[i] = expf(v[i] - m); s += e[i]; }
#pragma unroll
    for (int o = 16; o; o >>= 1) s += __shfl_xor_sync(0xffffffffu, s, o);
    if (lane == 0) sred[wid] = s;
    __syncthreads();
    s = 0.f;
#pragma unroll
    for (int w = 0; w < 8; w++) s += sred[w];
    float inv = 1.0f / s;
    n = 0;
    for (int i = tid; i < T; i += 256) {
        const float p = e[n] * inv;
        base[i] = p;
        const bf16 hi = __float2bfloat16_rn(p);
        ph[i] = hi;
        pl[i] = __float2bfloat16_rn(p - __bfloat162float(hi));
        n++;
    }
}

// ================= pipelined AV =================
// dynamic smem per stage: PsH/PsL 128x40 (10240 B each) + VsH/VsL 32x72 (4608 B each) = 29696
constexpr uint32_t AV_PP = 128 * 40 * 2;        // 10240
constexpr uint32_t AV_VP = 32 * 72 * 2;         // 4608
constexpr uint32_t AV_ST = 2 * AV_PP + 2 * AV_VP;   // 29696
constexpr uint32_t AV_SMEM = 2 * AV_ST;         // 59392

__global__ __launch_bounds__(256) void av_hmma()
{
    extern __shared__ char dsm[];
    const uint32_t sm = smem_addr(dsm);
    const int tid = threadIdx.x;
    const int wid = tid >> 5, lane = tid & 31;
    const int wm = wid & 3, wn = wid >> 2;
    const int bh = blockIdx.y, b = bh >> 3, h = bh & 7;
    const int q0 = blockIdx.x * 128;
    const int a_r = lane & 15, a_c = (lane >> 4) * 8;
    const int tr = lane >> 2, tc = (lane & 3) * 2;

    float acc[2][4][4];
#pragma unroll
    for (int mi = 0; mi < 2; mi++)
#pragma unroll
        for (int ni = 0; ni < 4; ni++)
#pragma unroll
            for (int r = 0; r < 4; r++) acc[mi][ni][r] = 0.f;

    const int pr0 = tid >> 2, pc0 = (tid & 3) * 8;
    const int pr1 = (tid + 256) >> 2, pc1 = ((tid + 256) & 3) * 8;
    const int vr = tid >> 3, vc = (tid & 7) * 8;

    auto load_stage = [&](int st, int k0) {
        const uint32_t base = sm + st * AV_ST;
#pragma unroll
        for (int i = 0; i < 2; i++) {
            const int row = i ? pr1 : pr0, c8 = i ? pc1 : pc0;
            const int q = q0 + row;
            const int qc = (q < T) ? q : (T - 1);
            const int pb = (q < T) ? 16 : 0;
            const size_t off = ((size_t)bh * T + qc) * TP + k0 + c8;
            const uint32_t so = (row * 40 + c8) * 2;
            cp16(base + so,         g_pH + off, pb);
            cp16(base + AV_PP + so, g_pL + off, pb);
        }
        {
            const int kv = k0 + vr;
            const int kc = (kv < T) ? kv : (T - 1);
            const int vb = (kv < T) ? 16 : 0;
            const size_t off = ((size_t)(b * T + kc)) * 512 + h * 64 + vc;
            const uint32_t so = (vr * 72 + vc) * 2;
            cp16(base + 2 * AV_PP + so,         g_fvH + off, vb);
            cp16(base + 2 * AV_PP + AV_VP + so, g_fvL + off, vb);
        }
    };

    load_stage(0, 0);
    CP_COMMIT();

    constexpr int NCHUNK = TP / 32;   // 25
    for (int chunk = 0; chunk < NCHUNK; chunk++) {
        const int st = chunk & 1;
        if (chunk + 1 < NCHUNK) {
            load_stage(st ^ 1, (chunk + 1) * 32);
            CP_COMMIT();
            CP_WAIT(1);
        } else {
            CP_WAIT(0);
        }
        __syncthreads();

        bf16 (*PsH)[40] = (bf16(*)[40])(dsm + st * AV_ST);
        bf16 (*PsL)[40] = (bf16(*)[40])(dsm + st * AV_ST + AV_PP);
        bf16 (*VsH)[72] = (bf16(*)[72])(dsm + st * AV_ST + 2 * AV_PP);
        bf16 (*VsL)[72] = (bf16(*)[72])(dsm + st * AV_ST + 2 * AV_PP + AV_VP);

        uint32_t ah[2][2][4], al[2][2][4];
#pragma unroll
        for (int mi = 0; mi < 2; mi++) {
            const int r = wm * 32 + mi * 16 + a_r;
#pragma unroll
            for (int ks = 0; ks < 2; ks++) {
                const int c = ks * 16 + a_c;
                ldsm_x4(ah[mi][ks], smem_addr(&PsH[r][c]));
                ldsm_x4(al[mi][ks], smem_addr(&PsL[r][c]));
            }
        }
#pragma unroll
        for (int ni = 0; ni < 4; ni++) {
            const int nb = wn * 32 + ni * 8;
            uint32_t bh4[4], bl4[4];
            ldsm_x4_t(bh4, smem_addr(&VsH[lane][nb]));
            ldsm_x4_t(bl4, smem_addr(&VsL[lane][nb]));
#pragma unroll
            for (int mi = 0; mi < 2; mi++) {
#pragma unroll
                for (int ks = 0; ks < 2; ks++) {
                    mma_bf16(acc[mi][ni], ah[mi][ks], bh4[2 * ks], bh4[2 * ks + 1]);
                    mma_bf16(acc[mi][ni], ah[mi][ks], bl4[2 * ks], bl4[2 * ks + 1]);
                    mma_bf16(acc[mi][ni], al[mi][ks], bh4[2 * ks], bh4[2 * ks + 1]);
                }
            }
        }
        __syncthreads();
    }

#pragma unroll
    for (int mi = 0; mi < 2; mi++) {
#pragma unroll
        for (int ni = 0; ni < 4; ni++) {
            const int n = wn * 32 + ni * 8 + tc;
#pragma unroll
            for (int half = 0; half < 2; half++) {
                const int q = q0 + wm * 32 + mi * 16 + tr + half * 8;
                if (q >= T) continue;
                const float x = acc[mi][ni][half * 2 + 0];
                const float y = acc[mi][ni][half * 2 + 1];
                uint32_t hi, lo; split2(x, y, hi, lo);
                const size_t off = ((size_t)(b * T + q)) * 512 + h * 64 + n;
                *(uint32_t*)(g_xaH + off) = hi;
                *(uint32_t*)(g_xaL + off) = lo;
            }
        }
    }
}

// ---------------- launcher ----------------
extern "C" void kernel_launch(void* const* d_in, const int* in_sizes, int n_in,
                              void* d_out, int out_size)
{
    const float* x_head = (const float*)d_in[0];
    const float* x_tail = (const float*)d_in[1];
    const int*   ids    = (const int*)  d_in[2];
    const float* Wh     = (const float*)d_in[3];
    const float* bh     = (const float*)d_in[4];
    const float* Wv     = (const float*)d_in[5];
    const float* bv     = (const float*)d_in[6];
    const float* Wo     = (const float*)d_in[7];
    const float* bo     = (const float*)d_in[8];
    const float* rel    = (const float*)d_in[9];
    const float* colh   = (const float*)d_in[10];
    const float* colt   = (const float*)d_in[11];
    const float* bias   = (const float*)d_in[12];

    float* out = (float*)d_out;
    float* FR  = out + X_ELEMS;

    bf16 *xhH, *xhL, *xtH, *xtL, *WhH, *WhL, *WvH, *WvL, *WoH, *WoL;
    bf16 *fhH, *fhL, *ftH, *ftL, *fvH, *fvL, *xaH, *xaL;
    cudaGetSymbolAddress((void**)&xhH, g_xhH); cudaGetSymbolAddress((void**)&xhL, g_xhL);
    cudaGetSymbolAddress((void**)&xtH, g_xtH); cudaGetSymbolAddress((void**)&xtL, g_xtL);
    cudaGetSymbolAddress((void**)&WhH, g_WhH); cudaGetSymbolAddress((void**)&WhL, g_WhL);
    cudaGetSymbolAddress((void**)&WvH, g_WvH); cudaGetSymbolAddress((void**)&WvL, g_WvL);
    cudaGetSymbolAddress((void**)&WoH, g_WoH); cudaGetSymbolAddress((void**)&WoL, g_WoL);
    cudaGetSymbolAddress((void**)&fhH, g_fhH); cudaGetSymbolAddress((void**)&fhL, g_fhL);
    cudaGetSymbolAddress((void**)&ftH, g_ftH); cudaGetSymbolAddress((void**)&ftL, g_ftL);
    cudaGetSymbolAddress((void**)&fvH, g_fvH); cudaGetSymbolAddress((void**)&fvL, g_fvL);
    cudaGetSymbolAddress((void**)&xaH, g_xaH); cudaGetSymbolAddress((void**)&xaL, g_xaL);

    cudaFuncSetAttribute(gemm_batched, cudaFuncAttributeMaxDynamicSharedMemorySize, GEMM_SMEM);
    cudaFuncSetAttribute(logits_hmma, cudaFuncAttributeMaxDynamicSharedMemorySize, LOGITS_SMEM);
    cudaFuncSetAttribute(av_hmma, cudaFuncAttributeMaxDynamicSharedMemorySize, AV_SMEM);

    const int nx4 = BT * 512 / 4;
    // launches 1-4
    convert_kernel<<<(nx4 + 255) / 256, 256>>>(x_head, xhH, xhL, nx4);
    convert_kernel<<<(nx4 + 255) / 256, 256>>>(x_tail, xtH, xtL, nx4);
    convert_w3_kernel<<<dim3(256, 3), 256>>>(Wh, Wv, Wo, WhH, WhL, WvH, WvL, WoH, WoL);
    gather_kernel2<<<(BHT * 32 + 255) / 256, 256>>>(colh, colt, ids);

    // launch 5: batched projections (profiled by ncu -s 5 -c 1)
    Jobs3 pj;
    pj.j[0] = { xhH, xhL, WhH, WhL, bh, rel,     nullptr, fhH, fhL };
    pj.j[1] = { xtH, xtL, WhH, WhL, bh, nullptr, nullptr, ftH, ftL };
    pj.j[2] = { xtH, xtL, WvH, WvL, bv, nullptr, nullptr, fvH, fvL };
    gemm_batched<<<dim3(4, (BT + 127) / 128, 3), 256, GEMM_SMEM>>>(pj, BT);

    // launch 6: logits
    dim3 gLog((T + 127) / 128, (T + 127) / 128, B * H);
    logits_hmma<<<gLog, 256, LOGITS_SMEM>>>(bias, FR);

    // launch 7: softmax
    softmax_kernel<<<B * H * T, 256>>>(FR);

    // launch 8: AV
    dim3 gAV((T + 127) / 128, B * H);
    av_hmma<<<gAV, 256, AV_SMEM>>>();

    // launch 9: output projection
    Jobs3 oj;
    oj.j[0] = { xaH, xaL, WoH, WoL, bo, nullptr, out, nullptr, nullptr };
    oj.j[1] = oj.j[0];
    oj.j[2] = oj.j[0];
    gemm_batched<<<dim3(4, (BT + 127) / 128, 1), 256, GEMM_SMEM>>>(oj, BT);
}